// round 2
// baseline (speedup 1.0000x reference)
#include <cuda_runtime.h>
#include <math.h>

#define BATCH 4
#define SEQ 1024
#define DMODEL 512
#define NHEAD 8
#define DHEAD 64
#define DINNER 1024
#define NLAYERS 2
#define NTOK (BATCH*SEQ)          // 4096
#define EPS 1e-3f
#define INV_TEMPER 0.044194173824159216f   // 1/sqrt(512)

// ------------------------- scratch (device globals; no runtime alloc) -----
__device__ float g_x  [NTOK*DMODEL];       // current activations
__device__ float g_q  [NHEAD*NTOK*DHEAD];
__device__ float g_k  [NHEAD*NTOK*DHEAD];
__device__ float g_v  [NHEAD*NTOK*DHEAD];
__device__ float g_att[NTOK*DMODEL];       // concat attention out
__device__ float g_h  [NTOK*DINNER];       // FFN hidden
__device__ float g_o  [NTOK*DMODEL];       // FFN out

// ------------------------- x + pos_enc ------------------------------------
__global__ void add_pos_kernel(const float* __restrict__ x,
                               const float* __restrict__ pos,
                               float* __restrict__ y)
{
    int idx = blockIdx.x * 512 + threadIdx.x;          // 4096 blocks x 512
    y[idx] = x[idx] + pos[idx & (SEQ*DMODEL - 1)];     // 2^19 mask
}

// ------------------------- tiled SGEMM (64x64x16, 4x4/thread) -------------
// C[M,N] = A[M,K] * op(B),  op(B)=B[K,N] (NN) or B[N,K]^T (NT)
// gridDim.z batches B and C by strideB/strideC (A shared).
template<bool TRANSB, bool RELU, bool HASBIAS>
__global__ void sgemm64(const float* __restrict__ A, const float* __restrict__ B,
                        float* __restrict__ C, const float* __restrict__ bias,
                        int M, int N, int K, long strideB, long strideC)
{
    const int bz = blockIdx.z;
    B += (long)bz * strideB;
    C += (long)bz * strideC;
    const int bm = blockIdx.y * 64;
    const int bn = blockIdx.x * 64;
    const int tid = threadIdx.x;           // 256 threads
    __shared__ float As[16][65];
    __shared__ float Bs[16][65];
    const int tr = tid / 16;               // 0..15
    const int tc = tid % 16;               // 0..15
    float acc[4][4] = {};

    const int arow = tid >> 2;             // 0..63
    const int acol = (tid & 3) << 2;       // 0,4,8,12

    for (int k0 = 0; k0 < K; k0 += 16) {
        float4 av = *(const float4*)(A + (long)(bm + arow) * K + k0 + acol);
        As[acol+0][arow] = av.x;
        As[acol+1][arow] = av.y;
        As[acol+2][arow] = av.z;
        As[acol+3][arow] = av.w;
        if (!TRANSB) {
            const int brow = tid >> 4;           // k: 0..15
            const int bcol = (tid & 15) << 2;    // n: 0..60
            float4 bv = *(const float4*)(B + (long)(k0 + brow) * N + bn + bcol);
            Bs[brow][bcol+0] = bv.x;
            Bs[brow][bcol+1] = bv.y;
            Bs[brow][bcol+2] = bv.z;
            Bs[brow][bcol+3] = bv.w;
        } else {
            const int brow = tid >> 2;           // n: 0..63
            const int bcol = (tid & 3) << 2;     // k: 0..12
            float4 bv = *(const float4*)(B + (long)(bn + brow) * K + k0 + bcol);
            Bs[bcol+0][brow] = bv.x;
            Bs[bcol+1][brow] = bv.y;
            Bs[bcol+2][brow] = bv.z;
            Bs[bcol+3][brow] = bv.w;
        }
        __syncthreads();
        #pragma unroll
        for (int k = 0; k < 16; ++k) {
            float ra[4], rb[4];
            #pragma unroll
            for (int i = 0; i < 4; ++i) ra[i] = As[k][tr*4 + i];
            #pragma unroll
            for (int j = 0; j < 4; ++j) rb[j] = Bs[k][tc*4 + j];
            #pragma unroll
            for (int i = 0; i < 4; ++i)
                #pragma unroll
                for (int j = 0; j < 4; ++j)
                    acc[i][j] += ra[i] * rb[j];
        }
        __syncthreads();
    }

    #pragma unroll
    for (int i = 0; i < 4; ++i) {
        const long crow = bm + tr*4 + i;
        #pragma unroll
        for (int j = 0; j < 4; ++j) {
            const int n = bn + tc*4 + j;
            float v = acc[i][j];
            if (HASBIAS) v += bias[n];
            if (RELU)    v = fmaxf(v, 0.f);
            C[crow * N + n] = v;
        }
    }
}

// ------------------------- fused attention --------------------------------
// grid: (SEQ/TQ, BATCH, NHEAD), block 128. Q/K/V layout: [h][b*SEQ+l][64].
// Writes concat-head output O[b,l, h*64+v].
#define TQ 8
__global__ void attn_kernel(const float* __restrict__ Q, const float* __restrict__ K,
                            const float* __restrict__ V, float* __restrict__ O)
{
    const int h = blockIdx.z, b = blockIdx.y;
    const int q0 = blockIdx.x * TQ;
    const int tid = threadIdx.x;
    __shared__ float sq[TQ][64];
    __shared__ float sc[TQ][SEQ];
    __shared__ float red[128];
    __shared__ float pacc[2][TQ][64];

    const long base = ((long)h * NTOK + (long)b * SEQ) * DHEAD;

    for (int i = tid; i < TQ*64; i += 128)
        sq[i >> 6][i & 63] = Q[base + (long)(q0 + (i >> 6)) * 64 + (i & 63)];
    __syncthreads();

    // ---- scores: each thread owns m = tid, tid+128, ...
    for (int m = tid; m < SEQ; m += 128) {
        float4 kreg[16];
        const float4* kr = (const float4*)(K + base + (long)m * 64);
        #pragma unroll
        for (int t = 0; t < 16; ++t) kreg[t] = kr[t];
        #pragma unroll
        for (int q = 0; q < TQ; ++q) {
            const float4* qv = (const float4*)sq[q];
            float d = 0.f;
            #pragma unroll
            for (int t = 0; t < 16; ++t) {
                float4 a = qv[t], c = kreg[t];
                d += a.x*c.x + a.y*c.y + a.z*c.z + a.w*c.w;
            }
            sc[q][m] = d * INV_TEMPER;
        }
    }
    __syncthreads();

    // ---- softmax per q row
    for (int q = 0; q < TQ; ++q) {
        float mx = -INFINITY;
        for (int m = tid; m < SEQ; m += 128) mx = fmaxf(mx, sc[q][m]);
        red[tid] = mx; __syncthreads();
        for (int s = 64; s > 0; s >>= 1) {
            if (tid < s) red[tid] = fmaxf(red[tid], red[tid+s]);
            __syncthreads();
        }
        mx = red[0]; __syncthreads();
        float sum = 0.f;
        for (int m = tid; m < SEQ; m += 128) {
            float e = expf(sc[q][m] - mx);
            sc[q][m] = e;
            sum += e;
        }
        red[tid] = sum; __syncthreads();
        for (int s = 64; s > 0; s >>= 1) {
            if (tid < s) red[tid] += red[tid+s];
            __syncthreads();
        }
        float inv = 1.f / red[0]; __syncthreads();
        for (int m = tid; m < SEQ; m += 128) sc[q][m] *= inv;
        __syncthreads();
    }

    // ---- P @ V : split m-range in halves; thread = (half, vdim)
    const int g = tid >> 6, v = tid & 63;
    float acc[TQ] = {};
    const int m0 = g * (SEQ/2), m1 = m0 + (SEQ/2);
    for (int m = m0; m < m1; ++m) {
        float vv = V[base + (long)m * 64 + v];
        #pragma unroll
        for (int q = 0; q < TQ; ++q) acc[q] += sc[q][m] * vv;
    }
    #pragma unroll
    for (int q = 0; q < TQ; ++q) pacc[g][q][v] = acc[q];
    __syncthreads();
    if (tid < 64) {
        #pragma unroll
        for (int q = 0; q < TQ; ++q) {
            float r = pacc[0][q][tid] + pacc[1][q][tid];
            O[(long)(b*SEQ + q0 + q) * DMODEL + h*64 + tid] = r;
        }
    }
}

// ------------------------- residual + LayerNorm ---------------------------
// y = (z - mu) / (std_unbiased + eps) * gamma + beta, z = X + R
__global__ void ln_kernel(const float* __restrict__ X, const float* __restrict__ R,
                          const float* __restrict__ gamma, const float* __restrict__ beta,
                          float* __restrict__ Y)
{
    const long row = blockIdx.x;
    const int tid = threadIdx.x;           // 128 threads, 4 elems each
    __shared__ float red[128];
    const int i = tid * 4;
    float4 a = *(const float4*)(X + row*DMODEL + i);
    float4 b = *(const float4*)(R + row*DMODEL + i);
    float z0 = a.x + b.x, z1 = a.y + b.y, z2 = a.z + b.z, z3 = a.w + b.w;

    red[tid] = z0 + z1 + z2 + z3; __syncthreads();
    for (int s = 64; s > 0; s >>= 1) {
        if (tid < s) red[tid] += red[tid+s];
        __syncthreads();
    }
    float mu = red[0] * (1.f / DMODEL); __syncthreads();

    float d0 = z0-mu, d1 = z1-mu, d2 = z2-mu, d3 = z3-mu;
    red[tid] = d0*d0 + d1*d1 + d2*d2 + d3*d3; __syncthreads();
    for (int s = 64; s > 0; s >>= 1) {
        if (tid < s) red[tid] += red[tid+s];
        __syncthreads();
    }
    float sigma = sqrtf(red[0] * (1.f / (DMODEL - 1)));   // unbiased (ddof=1)
    float sc = 1.f / (sigma + EPS);

    float4 g4 = *(const float4*)(gamma + i);
    float4 be = *(const float4*)(beta + i);
    float4 y;
    y.x = d0 * sc * g4.x + be.x;
    y.y = d1 * sc * g4.y + be.y;
    y.z = d2 * sc * g4.z + be.z;
    y.w = d3 * sc * g4.w + be.w;
    *(float4*)(Y + row*DMODEL + i) = y;
}

// ------------------------- launch ------------------------------------------
extern "C" void kernel_launch(void* const* d_in, const int* in_sizes, int n_in,
                              void* d_out, int out_size)
{
    (void)in_sizes; (void)n_in; (void)out_size;
    const float* x    = (const float*)d_in[0];
    const float* pos  = (const float*)d_in[1];
    const float* wq   = (const float*)d_in[2];
    const float* wk   = (const float*)d_in[3];
    const float* wv   = (const float*)d_in[4];
    const float* ln1a = (const float*)d_in[5];
    const float* ln1b = (const float*)d_in[6];
    const float* w1   = (const float*)d_in[7];
    const float* b1   = (const float*)d_in[8];
    const float* w2   = (const float*)d_in[9];
    const float* b2   = (const float*)d_in[10];
    const float* ln2a = (const float*)d_in[11];
    const float* ln2b = (const float*)d_in[12];
    float* out = (float*)d_out;

    float *gx, *gq, *gk, *gv, *ga, *gh, *go;
    cudaGetSymbolAddress((void**)&gx, g_x);
    cudaGetSymbolAddress((void**)&gq, g_q);
    cudaGetSymbolAddress((void**)&gk, g_k);
    cudaGetSymbolAddress((void**)&gv, g_v);
    cudaGetSymbolAddress((void**)&ga, g_att);
    cudaGetSymbolAddress((void**)&gh, g_h);
    cudaGetSymbolAddress((void**)&go, g_o);

    add_pos_kernel<<<NTOK*DMODEL/512, 512>>>(x, pos, gx);

    const long wqkv_head  = (long)DMODEL * DHEAD;          // 32768
    const long wqkv_layer = (long)NHEAD * wqkv_head;
    const long qkv_head   = (long)NTOK * DHEAD;            // 262144

    for (int i = 0; i < NLAYERS; ++i) {
        // QKV projections: per-head GEMM [4096,512]x[512,64]
        dim3 gqkv(1, NTOK/64, NHEAD);
        sgemm64<false,false,false><<<gqkv, 256>>>(gx, wq + i*wqkv_layer, gq, nullptr,
                                                  NTOK, DHEAD, DMODEL, wqkv_head, qkv_head);
        sgemm64<false,false,false><<<gqkv, 256>>>(gx, wk + i*wqkv_layer, gk, nullptr,
                                                  NTOK, DHEAD, DMODEL, wqkv_head, qkv_head);
        sgemm64<false,false,false><<<gqkv, 256>>>(gx, wv + i*wqkv_layer, gv, nullptr,
                                                  NTOK, DHEAD, DMODEL, wqkv_head, qkv_head);

        // attention + concat heads
        attn_kernel<<<dim3(SEQ/TQ, BATCH, NHEAD), 128>>>(gq, gk, gv, ga);

        // x = LN(attn_out + residual)
        ln_kernel<<<NTOK, 128>>>(ga, gx, ln1a + i*DMODEL, ln1b + i*DMODEL, gx);

        // FFN
        sgemm64<true,true,true><<<dim3(DINNER/64, NTOK/64, 1), 256>>>(
            gx, w1 + (long)i*DINNER*DMODEL, gh, b1 + i*DINNER,
            NTOK, DINNER, DMODEL, 0, 0);
        sgemm64<true,false,true><<<dim3(DMODEL/64, NTOK/64, 1), 256>>>(
            gh, w2 + (long)i*DMODEL*DINNER, go, b2 + i*DMODEL,
            NTOK, DMODEL, DINNER, 0, 0);

        // x = LN(ffn_out + x)
        ln_kernel<<<NTOK, 128>>>(go, gx, ln2a + i*DMODEL, ln2b + i*DMODEL, gx);
    }

    cudaMemcpyAsync(out, gx, (size_t)NTOK*DMODEL*sizeof(float),
                    cudaMemcpyDeviceToDevice);
}

// round 3
// speedup vs baseline: 1.0023x; 1.0023x over previous
#include <cuda_runtime.h>
#include <math.h>

#define BATCH 4
#define SEQ 1024
#define DMODEL 512
#define NHEAD 8
#define DHEAD 64
#define DINNER 1024
#define NLAYERS 2
#define NTOK (BATCH*SEQ)          // 4096
#define EPS 1e-3f
#define INV_TEMPER 0.044194173824159216f   // 1/sqrt(512)

// ------------------------- scratch (device globals; no runtime alloc) -----
__device__ float g_x  [NTOK*DMODEL];       // current activations
__device__ float g_q  [NHEAD*NTOK*DHEAD];
__device__ float g_k  [NHEAD*NTOK*DHEAD];
__device__ float g_v  [NHEAD*NTOK*DHEAD];
__device__ float g_att[NTOK*DMODEL];       // concat attention out
__device__ float g_h  [NTOK*DINNER];       // FFN hidden
__device__ float g_o  [NTOK*DMODEL];       // FFN out

// ------------------------- x + pos_enc ------------------------------------
__global__ void add_pos_kernel(const float* __restrict__ x,
                               const float* __restrict__ pos,
                               float* __restrict__ y)
{
    int idx = blockIdx.x * 512 + threadIdx.x;          // 4096 blocks x 512
    y[idx] = x[idx] + pos[idx & (SEQ*DMODEL - 1)];     // 2^19 mask
}

// ------------------------- tiled SGEMM (64x64x16, 4x4/thread) -------------
// C[M,N] = A[M,K] * op(B),  op(B)=B[K,N] (NN) or B[N,K]^T (NT)
// gridDim.z batches B and C by strideB/strideC (A shared).
template<bool TRANSB, bool RELU, bool HASBIAS>
__global__ void sgemm64(const float* __restrict__ A, const float* __restrict__ B,
                        float* __restrict__ C, const float* __restrict__ bias,
                        int M, int N, int K, long strideB, long strideC)
{
    const int bz = blockIdx.z;
    B += (long)bz * strideB;
    C += (long)bz * strideC;
    const int bm = blockIdx.y * 64;
    const int bn = blockIdx.x * 64;
    const int tid = threadIdx.x;           // 256 threads
    __shared__ float As[16][65];
    __shared__ float Bs[16][65];
    const int tr = tid / 16;               // 0..15
    const int tc = tid % 16;               // 0..15
    float acc[4][4] = {};

    const int arow = tid >> 2;             // 0..63
    const int acol = (tid & 3) << 2;       // 0,4,8,12

    for (int k0 = 0; k0 < K; k0 += 16) {
        float4 av = *(const float4*)(A + (long)(bm + arow) * K + k0 + acol);
        As[acol+0][arow] = av.x;
        As[acol+1][arow] = av.y;
        As[acol+2][arow] = av.z;
        As[acol+3][arow] = av.w;
        if (!TRANSB) {
            const int brow = tid >> 4;           // k: 0..15
            const int bcol = (tid & 15) << 2;    // n: 0..60
            float4 bv = *(const float4*)(B + (long)(k0 + brow) * N + bn + bcol);
            Bs[brow][bcol+0] = bv.x;
            Bs[brow][bcol+1] = bv.y;
            Bs[brow][bcol+2] = bv.z;
            Bs[brow][bcol+3] = bv.w;
        } else {
            const int brow = tid >> 2;           // n: 0..63
            const int bcol = (tid & 3) << 2;     // k: 0..12
            float4 bv = *(const float4*)(B + (long)(bn + brow) * K + k0 + bcol);
            Bs[bcol+0][brow] = bv.x;
            Bs[bcol+1][brow] = bv.y;
            Bs[bcol+2][brow] = bv.z;
            Bs[bcol+3][brow] = bv.w;
        }
        __syncthreads();
        #pragma unroll
        for (int k = 0; k < 16; ++k) {
            float ra[4], rb[4];
            #pragma unroll
            for (int i = 0; i < 4; ++i) ra[i] = As[k][tr*4 + i];
            #pragma unroll
            for (int j = 0; j < 4; ++j) rb[j] = Bs[k][tc*4 + j];
            #pragma unroll
            for (int i = 0; i < 4; ++i)
                #pragma unroll
                for (int j = 0; j < 4; ++j)
                    acc[i][j] += ra[i] * rb[j];
        }
        __syncthreads();
    }

    #pragma unroll
    for (int i = 0; i < 4; ++i) {
        const long crow = bm + tr*4 + i;
        #pragma unroll
        for (int j = 0; j < 4; ++j) {
            const int n = bn + tc*4 + j;
            float v = acc[i][j];
            if (HASBIAS) v += bias[n];
            if (RELU)    v = fmaxf(v, 0.f);
            C[crow * N + n] = v;
        }
    }
}

// ------------------------- fused attention --------------------------------
// grid: (SEQ/TQ, BATCH, NHEAD), block 128. Q/K/V layout: [h][b*SEQ+l][64].
// Writes concat-head output O[b,l, h*64+v].
#define TQ 8
__global__ void attn_kernel(const float* __restrict__ Q, const float* __restrict__ K,
                            const float* __restrict__ V, float* __restrict__ O)
{
    const int h = blockIdx.z, b = blockIdx.y;
    const int q0 = blockIdx.x * TQ;
    const int tid = threadIdx.x;
    __shared__ float sq[TQ][64];
    __shared__ float sc[TQ][SEQ];
    __shared__ float red[128];
    __shared__ float pacc[2][TQ][64];

    const long base = ((long)h * NTOK + (long)b * SEQ) * DHEAD;

    for (int i = tid; i < TQ*64; i += 128)
        sq[i >> 6][i & 63] = Q[base + (long)(q0 + (i >> 6)) * 64 + (i & 63)];
    __syncthreads();

    // ---- scores: each thread owns m = tid, tid+128, ...
    for (int m = tid; m < SEQ; m += 128) {
        float4 kreg[16];
        const float4* kr = (const float4*)(K + base + (long)m * 64);
        #pragma unroll
        for (int t = 0; t < 16; ++t) kreg[t] = kr[t];
        #pragma unroll
        for (int q = 0; q < TQ; ++q) {
            const float4* qv = (const float4*)sq[q];
            float d = 0.f;
            #pragma unroll
            for (int t = 0; t < 16; ++t) {
                float4 a = qv[t], c = kreg[t];
                d += a.x*c.x + a.y*c.y + a.z*c.z + a.w*c.w;
            }
            sc[q][m] = d * INV_TEMPER;
        }
    }
    __syncthreads();

    // ---- softmax per q row
    for (int q = 0; q < TQ; ++q) {
        float mx = -INFINITY;
        for (int m = tid; m < SEQ; m += 128) mx = fmaxf(mx, sc[q][m]);
        red[tid] = mx; __syncthreads();
        for (int s = 64; s > 0; s >>= 1) {
            if (tid < s) red[tid] = fmaxf(red[tid], red[tid+s]);
            __syncthreads();
        }
        mx = red[0]; __syncthreads();
        float sum = 0.f;
        for (int m = tid; m < SEQ; m += 128) {
            float e = expf(sc[q][m] - mx);
            sc[q][m] = e;
            sum += e;
        }
        red[tid] = sum; __syncthreads();
        for (int s = 64; s > 0; s >>= 1) {
            if (tid < s) red[tid] += red[tid+s];
            __syncthreads();
        }
        float inv = 1.f / red[0]; __syncthreads();
        for (int m = tid; m < SEQ; m += 128) sc[q][m] *= inv;
        __syncthreads();
    }

    // ---- P @ V : split m-range in halves; thread = (half, vdim)
    const int g = tid >> 6, v = tid & 63;
    float acc[TQ] = {};
    const int m0 = g * (SEQ/2), m1 = m0 + (SEQ/2);
    for (int m = m0; m < m1; ++m) {
        float vv = V[base + (long)m * 64 + v];
        #pragma unroll
        for (int q = 0; q < TQ; ++q) acc[q] += sc[q][m] * vv;
    }
    #pragma unroll
    for (int q = 0; q < TQ; ++q) pacc[g][q][v] = acc[q];
    __syncthreads();
    if (tid < 64) {
        #pragma unroll
        for (int q = 0; q < TQ; ++q) {
            float r = pacc[0][q][tid] + pacc[1][q][tid];
            O[(long)(b*SEQ + q0 + q) * DMODEL + h*64 + tid] = r;
        }
    }
}

// ------------------------- residual + LayerNorm ---------------------------
// y = (z - mu) / (std_unbiased + eps) * gamma + beta, z = X + R
__global__ void ln_kernel(const float* __restrict__ X, const float* __restrict__ R,
                          const float* __restrict__ gamma, const float* __restrict__ beta,
                          float* __restrict__ Y)
{
    const long row = blockIdx.x;
    const int tid = threadIdx.x;           // 128 threads, 4 elems each
    __shared__ float red[128];
    const int i = tid * 4;
    float4 a = *(const float4*)(X + row*DMODEL + i);
    float4 b = *(const float4*)(R + row*DMODEL + i);
    float z0 = a.x + b.x, z1 = a.y + b.y, z2 = a.z + b.z, z3 = a.w + b.w;

    red[tid] = z0 + z1 + z2 + z3; __syncthreads();
    for (int s = 64; s > 0; s >>= 1) {
        if (tid < s) red[tid] += red[tid+s];
        __syncthreads();
    }
    float mu = red[0] * (1.f / DMODEL); __syncthreads();

    float d0 = z0-mu, d1 = z1-mu, d2 = z2-mu, d3 = z3-mu;
    red[tid] = d0*d0 + d1*d1 + d2*d2 + d3*d3; __syncthreads();
    for (int s = 64; s > 0; s >>= 1) {
        if (tid < s) red[tid] += red[tid+s];
        __syncthreads();
    }
    float sigma = sqrtf(red[0] * (1.f / (DMODEL - 1)));   // unbiased (ddof=1)
    float sc = 1.f / (sigma + EPS);

    float4 g4 = *(const float4*)(gamma + i);
    float4 be = *(const float4*)(beta + i);
    float4 y;
    y.x = d0 * sc * g4.x + be.x;
    y.y = d1 * sc * g4.y + be.y;
    y.z = d2 * sc * g4.z + be.z;
    y.w = d3 * sc * g4.w + be.w;
    *(float4*)(Y + row*DMODEL + i) = y;
}

// ------------------------- launch ------------------------------------------
extern "C" void kernel_launch(void* const* d_in, const int* in_sizes, int n_in,
                              void* d_out, int out_size)
{
    (void)in_sizes; (void)n_in; (void)out_size;
    const float* x    = (const float*)d_in[0];
    const float* pos  = (const float*)d_in[1];
    const float* wq   = (const float*)d_in[2];
    const float* wk   = (const float*)d_in[3];
    const float* wv   = (const float*)d_in[4];
    const float* ln1a = (const float*)d_in[5];
    const float* ln1b = (const float*)d_in[6];
    const float* w1   = (const float*)d_in[7];
    const float* b1   = (const float*)d_in[8];
    const float* w2   = (const float*)d_in[9];
    const float* b2   = (const float*)d_in[10];
    const float* ln2a = (const float*)d_in[11];
    const float* ln2b = (const float*)d_in[12];
    float* out = (float*)d_out;

    float *gx, *gq, *gk, *gv, *ga, *gh, *go;
    cudaGetSymbolAddress((void**)&gx, g_x);
    cudaGetSymbolAddress((void**)&gq, g_q);
    cudaGetSymbolAddress((void**)&gk, g_k);
    cudaGetSymbolAddress((void**)&gv, g_v);
    cudaGetSymbolAddress((void**)&ga, g_att);
    cudaGetSymbolAddress((void**)&gh, g_h);
    cudaGetSymbolAddress((void**)&go, g_o);

    add_pos_kernel<<<NTOK*DMODEL/512, 512>>>(x, pos, gx);

    const long wqkv_head  = (long)DMODEL * DHEAD;          // 32768
    const long wqkv_layer = (long)NHEAD * wqkv_head;
    const long qkv_head   = (long)NTOK * DHEAD;            // 262144

    for (int i = 0; i < NLAYERS; ++i) {
        // QKV projections: per-head GEMM [4096,512]x[512,64]
        dim3 gqkv(1, NTOK/64, NHEAD);
        sgemm64<false,false,false><<<gqkv, 256>>>(gx, wq + i*wqkv_layer, gq, nullptr,
                                                  NTOK, DHEAD, DMODEL, wqkv_head, qkv_head);
        sgemm64<false,false,false><<<gqkv, 256>>>(gx, wk + i*wqkv_layer, gk, nullptr,
                                                  NTOK, DHEAD, DMODEL, wqkv_head, qkv_head);
        sgemm64<false,false,false><<<gqkv, 256>>>(gx, wv + i*wqkv_layer, gv, nullptr,
                                                  NTOK, DHEAD, DMODEL, wqkv_head, qkv_head);

        // attention + concat heads
        attn_kernel<<<dim3(SEQ/TQ, BATCH, NHEAD), 128>>>(gq, gk, gv, ga);

        // x = LN(attn_out + residual)
        ln_kernel<<<NTOK, 128>>>(ga, gx, ln1a + i*DMODEL, ln1b + i*DMODEL, gx);

        // FFN
        sgemm64<true,true,true><<<dim3(DINNER/64, NTOK/64, 1), 256>>>(
            gx, w1 + (long)i*DINNER*DMODEL, gh, b1 + i*DINNER,
            NTOK, DINNER, DMODEL, 0, 0);
        sgemm64<true,false,true><<<dim3(DMODEL/64, NTOK/64, 1), 256>>>(
            gh, w2 + (long)i*DMODEL*DINNER, go, b2 + i*DMODEL,
            NTOK, DMODEL, DINNER, 0, 0);

        // x = LN(ffn_out + x)
        ln_kernel<<<NTOK, 128>>>(go, gx, ln2a + i*DMODEL, ln2b + i*DMODEL, gx);
    }

    cudaMemcpyAsync(out, gx, (size_t)NTOK*DMODEL*sizeof(float),
                    cudaMemcpyDeviceToDevice);
}

// round 4
// speedup vs baseline: 1.0023x; 1.0000x over previous
#include <cuda_runtime.h>
#include <math.h>

#define BATCH 4
#define SEQ 1024
#define DMODEL 512
#define NHEAD 8
#define DHEAD 64
#define DINNER 1024
#define NLAYERS 2
#define NTOK (BATCH*SEQ)          // 4096
#define EPS 1e-3f
#define INV_TEMPER 0.044194173824159216f   // 1/sqrt(512)

// ------------------------- scratch (device globals; no runtime alloc) -----
__device__ float g_x  [NTOK*DMODEL];       // current activations
__device__ float g_q  [NHEAD*NTOK*DHEAD];
__device__ float g_k  [NHEAD*NTOK*DHEAD];
__device__ float g_v  [NHEAD*NTOK*DHEAD];
__device__ float g_att[NTOK*DMODEL];       // concat attention out
__device__ float g_h  [NTOK*DINNER];       // FFN hidden
__device__ float g_o  [NTOK*DMODEL];       // FFN out

// ------------------------- x + pos_enc ------------------------------------
__global__ void add_pos_kernel(const float* __restrict__ x,
                               const float* __restrict__ pos,
                               float* __restrict__ y)
{
    int idx = blockIdx.x * 512 + threadIdx.x;          // 4096 blocks x 512
    y[idx] = x[idx] + pos[idx & (SEQ*DMODEL - 1)];     // 2^19 mask
}

// ------------------------- tiled SGEMM (64x64x16, 4x4/thread) -------------
// C[M,N] = A[M,K] * op(B),  op(B)=B[K,N] (NN) or B[N,K]^T (NT)
// gridDim.z batches B and C by strideB/strideC (A shared).
template<bool TRANSB, bool RELU, bool HASBIAS>
__global__ void sgemm64(const float* __restrict__ A, const float* __restrict__ B,
                        float* __restrict__ C, const float* __restrict__ bias,
                        int M, int N, int K, long strideB, long strideC)
{
    const int bz = blockIdx.z;
    B += (long)bz * strideB;
    C += (long)bz * strideC;
    const int bm = blockIdx.y * 64;
    const int bn = blockIdx.x * 64;
    const int tid = threadIdx.x;           // 256 threads
    __shared__ float As[16][65];
    __shared__ float Bs[16][65];
    const int tr = tid / 16;               // 0..15
    const int tc = tid % 16;               // 0..15
    float acc[4][4] = {};

    const int arow = tid >> 2;             // 0..63
    const int acol = (tid & 3) << 2;       // 0,4,8,12

    for (int k0 = 0; k0 < K; k0 += 16) {
        float4 av = *(const float4*)(A + (long)(bm + arow) * K + k0 + acol);
        As[acol+0][arow] = av.x;
        As[acol+1][arow] = av.y;
        As[acol+2][arow] = av.z;
        As[acol+3][arow] = av.w;
        if (!TRANSB) {
            const int brow = tid >> 4;           // k: 0..15
            const int bcol = (tid & 15) << 2;    // n: 0..60
            float4 bv = *(const float4*)(B + (long)(k0 + brow) * N + bn + bcol);
            Bs[brow][bcol+0] = bv.x;
            Bs[brow][bcol+1] = bv.y;
            Bs[brow][bcol+2] = bv.z;
            Bs[brow][bcol+3] = bv.w;
        } else {
            const int brow = tid >> 2;           // n: 0..63
            const int bcol = (tid & 3) << 2;     // k: 0..12
            float4 bv = *(const float4*)(B + (long)(bn + brow) * K + k0 + bcol);
            Bs[bcol+0][brow] = bv.x;
            Bs[bcol+1][brow] = bv.y;
            Bs[bcol+2][brow] = bv.z;
            Bs[bcol+3][brow] = bv.w;
        }
        __syncthreads();
        #pragma unroll
        for (int k = 0; k < 16; ++k) {
            float ra[4], rb[4];
            #pragma unroll
            for (int i = 0; i < 4; ++i) ra[i] = As[k][tr*4 + i];
            #pragma unroll
            for (int j = 0; j < 4; ++j) rb[j] = Bs[k][tc*4 + j];
            #pragma unroll
            for (int i = 0; i < 4; ++i)
                #pragma unroll
                for (int j = 0; j < 4; ++j)
                    acc[i][j] += ra[i] * rb[j];
        }
        __syncthreads();
    }

    #pragma unroll
    for (int i = 0; i < 4; ++i) {
        const long crow = bm + tr*4 + i;
        #pragma unroll
        for (int j = 0; j < 4; ++j) {
            const int n = bn + tc*4 + j;
            float v = acc[i][j];
            if (HASBIAS) v += bias[n];
            if (RELU)    v = fmaxf(v, 0.f);
            C[crow * N + n] = v;
        }
    }
}

// ------------------------- fused attention --------------------------------
// grid: (SEQ/TQ, BATCH, NHEAD), block 128. Q/K/V layout: [h][b*SEQ+l][64].
// Writes concat-head output O[b,l, h*64+v].
#define TQ 8
__global__ void attn_kernel(const float* __restrict__ Q, const float* __restrict__ K,
                            const float* __restrict__ V, float* __restrict__ O)
{
    const int h = blockIdx.z, b = blockIdx.y;
    const int q0 = blockIdx.x * TQ;
    const int tid = threadIdx.x;
    __shared__ float sq[TQ][64];
    __shared__ float sc[TQ][SEQ];
    __shared__ float red[128];
    __shared__ float pacc[2][TQ][64];

    const long base = ((long)h * NTOK + (long)b * SEQ) * DHEAD;

    for (int i = tid; i < TQ*64; i += 128)
        sq[i >> 6][i & 63] = Q[base + (long)(q0 + (i >> 6)) * 64 + (i & 63)];
    __syncthreads();

    // ---- scores: each thread owns m = tid, tid+128, ...
    for (int m = tid; m < SEQ; m += 128) {
        float4 kreg[16];
        const float4* kr = (const float4*)(K + base + (long)m * 64);
        #pragma unroll
        for (int t = 0; t < 16; ++t) kreg[t] = kr[t];
        #pragma unroll
        for (int q = 0; q < TQ; ++q) {
            const float4* qv = (const float4*)sq[q];
            float d = 0.f;
            #pragma unroll
            for (int t = 0; t < 16; ++t) {
                float4 a = qv[t], c = kreg[t];
                d += a.x*c.x + a.y*c.y + a.z*c.z + a.w*c.w;
            }
            sc[q][m] = d * INV_TEMPER;
        }
    }
    __syncthreads();

    // ---- softmax per q row
    for (int q = 0; q < TQ; ++q) {
        float mx = -INFINITY;
        for (int m = tid; m < SEQ; m += 128) mx = fmaxf(mx, sc[q][m]);
        red[tid] = mx; __syncthreads();
        for (int s = 64; s > 0; s >>= 1) {
            if (tid < s) red[tid] = fmaxf(red[tid], red[tid+s]);
            __syncthreads();
        }
        mx = red[0]; __syncthreads();
        float sum = 0.f;
        for (int m = tid; m < SEQ; m += 128) {
            float e = expf(sc[q][m] - mx);
            sc[q][m] = e;
            sum += e;
        }
        red[tid] = sum; __syncthreads();
        for (int s = 64; s > 0; s >>= 1) {
            if (tid < s) red[tid] += red[tid+s];
            __syncthreads();
        }
        float inv = 1.f / red[0]; __syncthreads();
        for (int m = tid; m < SEQ; m += 128) sc[q][m] *= inv;
        __syncthreads();
    }

    // ---- P @ V : split m-range in halves; thread = (half, vdim)
    const int g = tid >> 6, v = tid & 63;
    float acc[TQ] = {};
    const int m0 = g * (SEQ/2), m1 = m0 + (SEQ/2);
    for (int m = m0; m < m1; ++m) {
        float vv = V[base + (long)m * 64 + v];
        #pragma unroll
        for (int q = 0; q < TQ; ++q) acc[q] += sc[q][m] * vv;
    }
    #pragma unroll
    for (int q = 0; q < TQ; ++q) pacc[g][q][v] = acc[q];
    __syncthreads();
    if (tid < 64) {
        #pragma unroll
        for (int q = 0; q < TQ; ++q) {
            float r = pacc[0][q][tid] + pacc[1][q][tid];
            O[(long)(b*SEQ + q0 + q) * DMODEL + h*64 + tid] = r;
        }
    }
}

// ------------------------- residual + LayerNorm ---------------------------
// y = (z - mu) / (std_unbiased + eps) * gamma + beta, z = X + R
__global__ void ln_kernel(const float* __restrict__ X, const float* __restrict__ R,
                          const float* __restrict__ gamma, const float* __restrict__ beta,
                          float* __restrict__ Y)
{
    const long row = blockIdx.x;
    const int tid = threadIdx.x;           // 128 threads, 4 elems each
    __shared__ float red[128];
    const int i = tid * 4;
    float4 a = *(const float4*)(X + row*DMODEL + i);
    float4 b = *(const float4*)(R + row*DMODEL + i);
    float z0 = a.x + b.x, z1 = a.y + b.y, z2 = a.z + b.z, z3 = a.w + b.w;

    red[tid] = z0 + z1 + z2 + z3; __syncthreads();
    for (int s = 64; s > 0; s >>= 1) {
        if (tid < s) red[tid] += red[tid+s];
        __syncthreads();
    }
    float mu = red[0] * (1.f / DMODEL); __syncthreads();

    float d0 = z0-mu, d1 = z1-mu, d2 = z2-mu, d3 = z3-mu;
    red[tid] = d0*d0 + d1*d1 + d2*d2 + d3*d3; __syncthreads();
    for (int s = 64; s > 0; s >>= 1) {
        if (tid < s) red[tid] += red[tid+s];
        __syncthreads();
    }
    float sigma = sqrtf(red[0] * (1.f / (DMODEL - 1)));   // unbiased (ddof=1)
    float sc = 1.f / (sigma + EPS);

    float4 g4 = *(const float4*)(gamma + i);
    float4 be = *(const float4*)(beta + i);
    float4 y;
    y.x = d0 * sc * g4.x + be.x;
    y.y = d1 * sc * g4.y + be.y;
    y.z = d2 * sc * g4.z + be.z;
    y.w = d3 * sc * g4.w + be.w;
    *(float4*)(Y + row*DMODEL + i) = y;
}

// ------------------------- launch ------------------------------------------
extern "C" void kernel_launch(void* const* d_in, const int* in_sizes, int n_in,
                              void* d_out, int out_size)
{
    (void)in_sizes; (void)n_in; (void)out_size;
    const float* x    = (const float*)d_in[0];
    const float* pos  = (const float*)d_in[1];
    const float* wq   = (const float*)d_in[2];
    const float* wk   = (const float*)d_in[3];
    const float* wv   = (const float*)d_in[4];
    const float* ln1a = (const float*)d_in[5];
    const float* ln1b = (const float*)d_in[6];
    const float* w1   = (const float*)d_in[7];
    const float* b1   = (const float*)d_in[8];
    const float* w2   = (const float*)d_in[9];
    const float* b2   = (const float*)d_in[10];
    const float* ln2a = (const float*)d_in[11];
    const float* ln2b = (const float*)d_in[12];
    float* out = (float*)d_out;

    float *gx, *gq, *gk, *gv, *ga, *gh, *go;
    cudaGetSymbolAddress((void**)&gx, g_x);
    cudaGetSymbolAddress((void**)&gq, g_q);
    cudaGetSymbolAddress((void**)&gk, g_k);
    cudaGetSymbolAddress((void**)&gv, g_v);
    cudaGetSymbolAddress((void**)&ga, g_att);
    cudaGetSymbolAddress((void**)&gh, g_h);
    cudaGetSymbolAddress((void**)&go, g_o);

    add_pos_kernel<<<NTOK*DMODEL/512, 512>>>(x, pos, gx);

    const long wqkv_head  = (long)DMODEL * DHEAD;          // 32768
    const long wqkv_layer = (long)NHEAD * wqkv_head;
    const long qkv_head   = (long)NTOK * DHEAD;            // 262144

    for (int i = 0; i < NLAYERS; ++i) {
        // QKV projections: per-head GEMM [4096,512]x[512,64]
        dim3 gqkv(1, NTOK/64, NHEAD);
        sgemm64<false,false,false><<<gqkv, 256>>>(gx, wq + i*wqkv_layer, gq, nullptr,
                                                  NTOK, DHEAD, DMODEL, wqkv_head, qkv_head);
        sgemm64<false,false,false><<<gqkv, 256>>>(gx, wk + i*wqkv_layer, gk, nullptr,
                                                  NTOK, DHEAD, DMODEL, wqkv_head, qkv_head);
        sgemm64<false,false,false><<<gqkv, 256>>>(gx, wv + i*wqkv_layer, gv, nullptr,
                                                  NTOK, DHEAD, DMODEL, wqkv_head, qkv_head);

        // attention + concat heads
        attn_kernel<<<dim3(SEQ/TQ, BATCH, NHEAD), 128>>>(gq, gk, gv, ga);

        // x = LN(attn_out + residual)
        ln_kernel<<<NTOK, 128>>>(ga, gx, ln1a + i*DMODEL, ln1b + i*DMODEL, gx);

        // FFN
        sgemm64<true,true,true><<<dim3(DINNER/64, NTOK/64, 1), 256>>>(
            gx, w1 + (long)i*DINNER*DMODEL, gh, b1 + i*DINNER,
            NTOK, DINNER, DMODEL, 0, 0);
        sgemm64<true,false,true><<<dim3(DMODEL/64, NTOK/64, 1), 256>>>(
            gh, w2 + (long)i*DMODEL*DINNER, go, b2 + i*DMODEL,
            NTOK, DMODEL, DINNER, 0, 0);

        // x = LN(ffn_out + x)
        ln_kernel<<<NTOK, 128>>>(go, gx, ln2a + i*DMODEL, ln2b + i*DMODEL, gx);
    }

    cudaMemcpyAsync(out, gx, (size_t)NTOK*DMODEL*sizeof(float),
                    cudaMemcpyDeviceToDevice);
}

// round 5
// speedup vs baseline: 2.1904x; 2.1854x over previous
#include <cuda_runtime.h>
#include <math.h>

#define BATCH 4
#define SEQ 1024
#define DMODEL 512
#define NHEAD 8
#define DHEAD 64
#define DINNER 1024
#define NLAYERS 2
#define NTOK (BATCH*SEQ)          // 4096
#define EPS 1e-3f
#define INV_TEMPER 0.044194173824159216f   // 1/sqrt(512)

// ------------------------- scratch (device globals; no runtime alloc) -----
__device__ float g_x  [NTOK*DMODEL];
__device__ float g_q  [NHEAD*NTOK*DHEAD];
__device__ float g_k  [NHEAD*NTOK*DHEAD];
__device__ float g_v  [NHEAD*NTOK*DHEAD];
__device__ float g_att[NTOK*DMODEL];
__device__ float g_h  [NTOK*DINNER];
__device__ float g_o  [NTOK*DMODEL];

// ------------------------- x + pos_enc ------------------------------------
__global__ void add_pos_kernel(const float* __restrict__ x,
                               const float* __restrict__ pos,
                               float* __restrict__ y)
{
    int idx = blockIdx.x * 512 + threadIdx.x;
    y[idx] = x[idx] + pos[idx & (SEQ*DMODEL - 1)];
}

// ------------------------- SGEMM 128xBN, BK=16, double-buffered -----------
// C[M,N] = A[M,K] * op(B) (+bias)(+relu). op(B)=B[K,N] (NN) or B[N,K]^T (NT).
// 256 threads. Per thread: 8 rows (split tr4 / 64+tr4) x (4 or 8) cols.
#define STS_TILE(BUF, A0, A1, B0, B1)                                \
    As[BUF][ak+0][ar]=A0.x; As[BUF][ak+1][ar]=A0.y;                  \
    As[BUF][ak+2][ar]=A0.z; As[BUF][ak+3][ar]=A0.w;                  \
    As[BUF][ak+4][ar]=A1.x; As[BUF][ak+5][ar]=A1.y;                  \
    As[BUF][ak+6][ar]=A1.z; As[BUF][ak+7][ar]=A1.w;                  \
    if (!TRANSB) {                                                   \
        *(float4*)&Bs[BUF][b_r][b_k] = B0;                           \
        if (BN==128) *(float4*)&Bs[BUF][b_r][b_k+4] = B1;            \
    } else {                                                         \
        Bs[BUF][b_k+0][b_r]=B0.x; Bs[BUF][b_k+1][b_r]=B0.y;          \
        Bs[BUF][b_k+2][b_r]=B0.z; Bs[BUF][b_k+3][b_r]=B0.w;          \
        if (BN==128) {                                               \
            Bs[BUF][b_k+4][b_r]=B1.x; Bs[BUF][b_k+5][b_r]=B1.y;      \
            Bs[BUF][b_k+6][b_r]=B1.z; Bs[BUF][b_k+7][b_r]=B1.w;      \
        }                                                            \
    }

template<int BN, bool TRANSB, bool RELU, bool HASBIAS>
__global__ __launch_bounds__(256, 2)
void sgemm128(const float* __restrict__ A, const float* __restrict__ B,
              float* __restrict__ C, const float* __restrict__ bias,
              int M, int N, int K, long strideB, long strideC)
{
    constexpr int BM = 128, BK = 16;
    constexpr int BCOLG = (BN == 128) ? 2 : 1;
    constexpr int CJ = BCOLG * 4;

    B += (long)blockIdx.z * strideB;
    C += (long)blockIdx.z * strideC;
    const int bm = blockIdx.y * BM;
    const int bn = blockIdx.x * BN;
    const int tid = threadIdx.x;

    __shared__ float As[2][BK][BM];
    __shared__ float Bs[2][BK][BN];

    // A load mapping: 2 adjacent float4 per thread (32B contiguous)
    const int ar = tid & 127;
    const int ak = (tid >> 7) * 8;
    const float* Ap = A + (long)(bm + ar) * K + ak;

    // B load mapping
    int b_r, b_k;
    const float* Bp;
    if (!TRANSB) {
        b_r = tid >> 4;                       // k
        b_k = (tid & 15) * (BN / 16);         // n offset (8 or 4 floats)
        Bp = B + (long)b_r * N + (bn + b_k);
    } else {
        constexpr int NPT = BK * BN / 256;    // 8 (BN=128) or 4 (BN=64)
        b_r = tid % BN;                       // n
        b_k = (tid / BN) * NPT;               // k offset
        Bp = B + (long)(bn + b_r) * K + b_k;
    }

    const int tr4 = (tid >> 4) * 4;
    const int tc4 = (tid & 15) * 4;
    float acc[8][CJ];
    #pragma unroll
    for (int i = 0; i < 8; ++i)
        #pragma unroll
        for (int j = 0; j < CJ; ++j) acc[i][j] = 0.f;

    // prologue: tile 0
    {
        float4 a0 = *(const float4*)Ap;
        float4 a1 = *(const float4*)(Ap + 4);
        float4 b0 = *(const float4*)Bp;
        float4 b1 = {0,0,0,0};
        if (BN == 128) b1 = *(const float4*)(Bp + 4);
        STS_TILE(0, a0, a1, b0, b1);
    }
    __syncthreads();

    const int nt = K / BK;
    int buf = 0;
    float4 a0n, a1n, b0n, b1n;
    for (int t = 0; t < nt; ++t) {
        if (t + 1 < nt) {
            const int k0 = (t + 1) * BK;
            const float* bq = TRANSB ? (Bp + k0) : (Bp + (long)k0 * N);
            a0n = *(const float4*)(Ap + k0);
            a1n = *(const float4*)(Ap + k0 + 4);
            b0n = *(const float4*)bq;
            if (BN == 128) b1n = *(const float4*)(bq + 4);
        }
        #pragma unroll
        for (int k = 0; k < BK; ++k) {
            float4 aL = *(const float4*)&As[buf][k][tr4];
            float4 aH = *(const float4*)&As[buf][k][64 + tr4];
            float4 bL = *(const float4*)&Bs[buf][k][tc4];
            float av[8] = {aL.x,aL.y,aL.z,aL.w,aH.x,aH.y,aH.z,aH.w};
            float bv[CJ];
            bv[0]=bL.x; bv[1]=bL.y; bv[2]=bL.z; bv[3]=bL.w;
            if (BN == 128) {
                float4 bH = *(const float4*)&Bs[buf][k][64 + tc4];
                bv[4]=bH.x; bv[5]=bH.y; bv[6]=bH.z; bv[7]=bH.w;
            }
            #pragma unroll
            for (int i = 0; i < 8; ++i)
                #pragma unroll
                for (int j = 0; j < CJ; ++j)
                    acc[i][j] += av[i] * bv[j];
        }
        if (t + 1 < nt) {
            const int nb = buf ^ 1;
            STS_TILE(nb, a0n, a1n, b0n, b1n);
            __syncthreads();
            buf = nb;
        }
    }

    // epilogue
    #pragma unroll
    for (int i = 0; i < 8; ++i) {
        const int row = bm + ((i < 4) ? (tr4 + i) : (64 + tr4 + i - 4));
        #pragma unroll
        for (int cg = 0; cg < BCOLG; ++cg) {
            const int col = bn + cg * 64 + tc4;
            float4 r;
            r.x = acc[i][cg*4+0]; r.y = acc[i][cg*4+1];
            r.z = acc[i][cg*4+2]; r.w = acc[i][cg*4+3];
            if (HASBIAS) {
                float4 bb = *(const float4*)(bias + col);
                r.x += bb.x; r.y += bb.y; r.z += bb.z; r.w += bb.w;
            }
            if (RELU) {
                r.x = fmaxf(r.x, 0.f); r.y = fmaxf(r.y, 0.f);
                r.z = fmaxf(r.z, 0.f); r.w = fmaxf(r.w, 0.f);
            }
            *(float4*)(C + (long)row * N + col) = r;
        }
    }
}

// ------------------------- fused attention --------------------------------
// grid: (SEQ/16, BATCH, NHEAD), 256 threads. Q/K/V layout: [h][b*SEQ+l][64].
// Writes concat-head output O[b,l, h*64+v].
#define TQ 16
#define SCP 1028                      // padded sc row stride (bank-stagger)
#define ATT_SMEM ((TQ*SCP + TQ*64 + 4*TQ*64 + 16) * 4)

__global__ __launch_bounds__(256, 2)
void attn_kernel(const float* __restrict__ Q, const float* __restrict__ K,
                 const float* __restrict__ V, float* __restrict__ O)
{
    extern __shared__ float sm[];
    float* sc   = sm;                       // [TQ][SCP]
    float* sq   = sm + TQ*SCP;              // [TQ][64]
    float* pacc = sq + TQ*64;               // [4][TQ][64]
    float* sinv = pacc + 4*TQ*64;           // [TQ]

    const int h = blockIdx.z, b = blockIdx.y;
    const int q0 = blockIdx.x * TQ;
    const int tid = threadIdx.x;
    const long base = ((long)h * NTOK + (long)b * SEQ) * DHEAD;

    // load Q tile (contiguous 1024 floats)
    ((float4*)sq)[tid] = *(const float4*)(Q + base + (long)q0*64 + tid*4);
    __syncthreads();

    // ---- scores: thread owns 4 m rows; 16 q dots each
    #pragma unroll 1
    for (int mi = 0; mi < 4; ++mi) {
        const int m = tid + mi*256;
        float4 kreg[16];
        const float4* kr = (const float4*)(K + base + (long)m * 64);
        #pragma unroll
        for (int t = 0; t < 16; ++t) kreg[t] = kr[t];
        #pragma unroll
        for (int q = 0; q < TQ; ++q) {
            const float4* q4 = (const float4*)(sq + q*64);
            float4 d = {0.f,0.f,0.f,0.f};
            #pragma unroll
            for (int t = 0; t < 16; ++t) {
                float4 a = q4[t];
                d.x += a.x*kreg[t].x; d.y += a.y*kreg[t].y;
                d.z += a.z*kreg[t].z; d.w += a.w*kreg[t].w;
            }
            sc[q*SCP + m] = (d.x + d.y + d.z + d.w) * INV_TEMPER;
        }
    }
    __syncthreads();

    // ---- softmax: warp w handles q = 2w, 2w+1; shuffle reductions
    {
        const int warp = tid >> 5, lane = tid & 31;
        #pragma unroll
        for (int qi = 0; qi < 2; ++qi) {
            const int q = warp*2 + qi;
            float* row = sc + q*SCP;
            float mx = -INFINITY;
            #pragma unroll
            for (int j = 0; j < 32; ++j) mx = fmaxf(mx, row[lane + 32*j]);
            #pragma unroll
            for (int s = 16; s; s >>= 1) mx = fmaxf(mx, __shfl_xor_sync(0xffffffffu, mx, s));
            float sum = 0.f;
            #pragma unroll
            for (int j = 0; j < 32; ++j) {
                float e = __expf(row[lane + 32*j] - mx);
                row[lane + 32*j] = e;
                sum += e;
            }
            #pragma unroll
            for (int s = 16; s; s >>= 1) sum += __shfl_xor_sync(0xffffffffu, sum, s);
            if (lane == 0) sinv[q] = 1.f / sum;
        }
    }
    __syncthreads();

    // ---- P@V mini-GEMM: thread = (g m-quarter, q4 row-quad, vq col-quad)
    {
        const int g  = tid >> 6;
        const int q4 = (tid >> 4) & 3;
        const int vq = tid & 15;
        const float* r0 = sc + (q4*4+0)*SCP;
        const float* r1 = sc + (q4*4+1)*SCP;
        const float* r2 = sc + (q4*4+2)*SCP;
        const float* r3 = sc + (q4*4+3)*SCP;
        float4 acc0 = {0,0,0,0}, acc1 = {0,0,0,0}, acc2 = {0,0,0,0}, acc3 = {0,0,0,0};
        const int m0 = g * 256;
        #pragma unroll 4
        for (int m = m0; m < m0 + 256; ++m) {
            float4 vv = *(const float4*)(V + base + (long)m*64 + vq*4);
            float p0 = r0[m], p1 = r1[m], p2 = r2[m], p3 = r3[m];
            acc0.x += p0*vv.x; acc0.y += p0*vv.y; acc0.z += p0*vv.z; acc0.w += p0*vv.w;
            acc1.x += p1*vv.x; acc1.y += p1*vv.y; acc1.z += p1*vv.z; acc1.w += p1*vv.w;
            acc2.x += p2*vv.x; acc2.y += p2*vv.y; acc2.z += p2*vv.z; acc2.w += p2*vv.w;
            acc3.x += p3*vv.x; acc3.y += p3*vv.y; acc3.z += p3*vv.z; acc3.w += p3*vv.w;
        }
        *(float4*)&pacc[(g*TQ + q4*4+0)*64 + vq*4] = acc0;
        *(float4*)&pacc[(g*TQ + q4*4+1)*64 + vq*4] = acc1;
        *(float4*)&pacc[(g*TQ + q4*4+2)*64 + vq*4] = acc2;
        *(float4*)&pacc[(g*TQ + q4*4+3)*64 + vq*4] = acc3;
    }
    __syncthreads();

    // ---- reduce 4 partials, scale by 1/sum, write concat output
    #pragma unroll
    for (int s = tid; s < TQ*64; s += 256) {
        const int q = s >> 6;
        float r = (pacc[s] + pacc[TQ*64 + s] + pacc[2*TQ*64 + s] + pacc[3*TQ*64 + s])
                  * sinv[q];
        O[(long)(b*SEQ + q0 + q) * DMODEL + h*64 + (s & 63)] = r;
    }
}

// ------------------------- residual + LayerNorm ---------------------------
__global__ void ln_kernel(const float* __restrict__ X, const float* __restrict__ R,
                          const float* __restrict__ gamma, const float* __restrict__ beta,
                          float* __restrict__ Y)
{
    const long row = blockIdx.x;
    const int tid = threadIdx.x;           // 128 threads, 4 elems each
    __shared__ float red[128];
    const int i = tid * 4;
    float4 a = *(const float4*)(X + row*DMODEL + i);
    float4 b = *(const float4*)(R + row*DMODEL + i);
    float z0 = a.x + b.x, z1 = a.y + b.y, z2 = a.z + b.z, z3 = a.w + b.w;

    red[tid] = z0 + z1 + z2 + z3; __syncthreads();
    for (int s = 64; s > 0; s >>= 1) {
        if (tid < s) red[tid] += red[tid+s];
        __syncthreads();
    }
    float mu = red[0] * (1.f / DMODEL); __syncthreads();

    float d0 = z0-mu, d1 = z1-mu, d2 = z2-mu, d3 = z3-mu;
    red[tid] = d0*d0 + d1*d1 + d2*d2 + d3*d3; __syncthreads();
    for (int s = 64; s > 0; s >>= 1) {
        if (tid < s) red[tid] += red[tid+s];
        __syncthreads();
    }
    float sigma = sqrtf(red[0] * (1.f / (DMODEL - 1)));   // unbiased (ddof=1)
    float sc = 1.f / (sigma + EPS);

    float4 g4 = *(const float4*)(gamma + i);
    float4 be = *(const float4*)(beta + i);
    float4 y;
    y.x = d0 * sc * g4.x + be.x;
    y.y = d1 * sc * g4.y + be.y;
    y.z = d2 * sc * g4.z + be.z;
    y.w = d3 * sc * g4.w + be.w;
    *(float4*)(Y + row*DMODEL + i) = y;
}

// ------------------------- launch ------------------------------------------
extern "C" void kernel_launch(void* const* d_in, const int* in_sizes, int n_in,
                              void* d_out, int out_size)
{
    (void)in_sizes; (void)n_in; (void)out_size;
    const float* x    = (const float*)d_in[0];
    const float* pos  = (const float*)d_in[1];
    const float* wq   = (const float*)d_in[2];
    const float* wk   = (const float*)d_in[3];
    const float* wv   = (const float*)d_in[4];
    const float* ln1a = (const float*)d_in[5];
    const float* ln1b = (const float*)d_in[6];
    const float* w1   = (const float*)d_in[7];
    const float* b1   = (const float*)d_in[8];
    const float* w2   = (const float*)d_in[9];
    const float* b2   = (const float*)d_in[10];
    const float* ln2a = (const float*)d_in[11];
    const float* ln2b = (const float*)d_in[12];
    float* out = (float*)d_out;

    float *gx, *gq, *gk, *gv, *ga, *gh, *go;
    cudaGetSymbolAddress((void**)&gx, g_x);
    cudaGetSymbolAddress((void**)&gq, g_q);
    cudaGetSymbolAddress((void**)&gk, g_k);
    cudaGetSymbolAddress((void**)&gv, g_v);
    cudaGetSymbolAddress((void**)&ga, g_att);
    cudaGetSymbolAddress((void**)&gh, g_h);
    cudaGetSymbolAddress((void**)&go, g_o);

    static bool attr_set = false;
    if (!attr_set) {
        cudaFuncSetAttribute(attn_kernel,
                             cudaFuncAttributeMaxDynamicSharedMemorySize, ATT_SMEM);
        attr_set = true;
    }

    add_pos_kernel<<<NTOK*DMODEL/512, 512>>>(x, pos, gx);

    const long wqkv_head  = (long)DMODEL * DHEAD;
    const long wqkv_layer = (long)NHEAD * wqkv_head;
    const long qkv_head   = (long)NTOK * DHEAD;

    for (int i = 0; i < NLAYERS; ++i) {
        // QKV projections: per-head GEMM [4096,512]x[512,64], z = head
        dim3 gqkv(1, NTOK/128, NHEAD);
        sgemm128<64,false,false,false><<<gqkv, 256>>>(gx, wq + i*wqkv_layer, gq, nullptr,
                                                      NTOK, DHEAD, DMODEL, wqkv_head, qkv_head);
        sgemm128<64,false,false,false><<<gqkv, 256>>>(gx, wk + i*wqkv_layer, gk, nullptr,
                                                      NTOK, DHEAD, DMODEL, wqkv_head, qkv_head);
        sgemm128<64,false,false,false><<<gqkv, 256>>>(gx, wv + i*wqkv_layer, gv, nullptr,
                                                      NTOK, DHEAD, DMODEL, wqkv_head, qkv_head);

        // attention + concat heads
        attn_kernel<<<dim3(SEQ/TQ, BATCH, NHEAD), 256, ATT_SMEM>>>(gq, gk, gv, ga);

        // x = LN(attn_out + residual)
        ln_kernel<<<NTOK, 128>>>(ga, gx, ln1a + i*DMODEL, ln1b + i*DMODEL, gx);

        // FFN: h = relu(x @ w1^T + b1)  [4096,512]x[1024,512]^T
        sgemm128<128,true,true,true><<<dim3(DINNER/128, NTOK/128, 1), 256>>>(
            gx, w1 + (long)i*DINNER*DMODEL, gh, b1 + i*DINNER,
            NTOK, DINNER, DMODEL, 0, 0);
        // o = h @ w2^T + b2  [4096,1024]x[512,1024]^T
        sgemm128<64,true,false,true><<<dim3(DMODEL/64, NTOK/128, 1), 256>>>(
            gh, w2 + (long)i*DMODEL*DINNER, go, b2 + i*DMODEL,
            NTOK, DMODEL, DINNER, 0, 0);

        // x = LN(ffn_out + x)
        ln_kernel<<<NTOK, 128>>>(go, gx, ln2a + i*DMODEL, ln2b + i*DMODEL, gx);
    }

    cudaMemcpyAsync(out, gx, (size_t)NTOK*DMODEL*sizeof(float),
                    cudaMemcpyDeviceToDevice);
}

// round 6
// speedup vs baseline: 3.0798x; 1.4061x over previous
#include <cuda_runtime.h>
#include <cuda_bf16.h>
#include <math.h>
#include <stdint.h>

#define BATCH 4
#define SEQ 1024
#define DMODEL 512
#define NHEAD 8
#define DHEAD 64
#define DINNER 1024
#define NLAYERS 2
#define NTOK (BATCH*SEQ)          // 4096
#define EPS 1e-3f
#define INV_TEMPER 0.044194173824159216f   // 1/sqrt(512)

// ------------------------- scratch (device globals; no runtime alloc) -----
__device__ float g_x  [NTOK*DMODEL];
__device__ float g_q  [NHEAD*NTOK*DHEAD];
__device__ float g_k  [NHEAD*NTOK*DHEAD];
__device__ float g_v  [NHEAD*NTOK*DHEAD];
__device__ float g_att[NTOK*DMODEL];
__device__ float g_h  [NTOK*DINNER];
__device__ float g_o  [NTOK*DMODEL];
// transposed qkv weights: [L][H][DHEAD][DMODEL]
__device__ float g_wqt[NLAYERS*NHEAD*DHEAD*DMODEL];
__device__ float g_wkt[NLAYERS*NHEAD*DHEAD*DMODEL];
__device__ float g_wvt[NLAYERS*NHEAD*DHEAD*DMODEL];

// ------------------------- x + pos_enc ------------------------------------
__global__ void add_pos_kernel(const float* __restrict__ x,
                               const float* __restrict__ pos,
                               float* __restrict__ y)
{
    int idx = blockIdx.x * 512 + threadIdx.x;
    y[idx] = x[idx] + pos[idx & (SEQ*DMODEL - 1)];
}

// ------------------------- transpose [R,C] -> [C,R] per z-matrix ----------
__global__ void transpose_kernel(const float* __restrict__ in, float* __restrict__ out,
                                 int R, int C)
{
    __shared__ float tile[32][33];
    const float* ip = in  + (long)blockIdx.z * R * C;
    float*       op = out + (long)blockIdx.z * R * C;
    int c0 = blockIdx.x * 32, r0 = blockIdx.y * 32;
    for (int i = threadIdx.y; i < 32; i += 8)
        tile[i][threadIdx.x] = ip[(long)(r0 + i) * C + c0 + threadIdx.x];
    __syncthreads();
    for (int i = threadIdx.y; i < 32; i += 8)
        op[(long)(c0 + i) * R + r0 + threadIdx.x] = tile[threadIdx.x][i];
}

// ------------------------- mma helpers ------------------------------------
__device__ __forceinline__ void ldsm4(uint32_t* r, uint32_t addr)
{
    asm volatile("ldmatrix.sync.aligned.m8n8.x4.shared.b16 {%0,%1,%2,%3}, [%4];"
        : "=r"(r[0]), "=r"(r[1]), "=r"(r[2]), "=r"(r[3]) : "r"(addr));
}

__device__ __forceinline__ void mma_bf16(float* c, const uint32_t* a,
                                         uint32_t b0, uint32_t b1)
{
    asm volatile(
        "mma.sync.aligned.m16n8k16.row.col.f32.bf16.bf16.f32 "
        "{%0,%1,%2,%3}, {%4,%5,%6,%7}, {%8,%9}, {%0,%1,%2,%3};\n"
        : "+f"(c[0]), "+f"(c[1]), "+f"(c[2]), "+f"(c[3])
        : "r"(a[0]), "r"(a[1]), "r"(a[2]), "r"(a[3]), "r"(b0), "r"(b1));
}

__device__ __forceinline__ uint32_t pack_bf16(__nv_bfloat16 a, __nv_bfloat16 b)
{
    __nv_bfloat162 t = __halves2bfloat162(a, b);
    return *(uint32_t*)&t;
}

// swizzled byte offset inside a [rows][32 bf16] plane (64B rows, 4x16B chunks)
__device__ __forceinline__ int swoff(int row, int chunk)
{
    return row * 64 + ((chunk ^ ((row >> 1) & 3)) * 16);
}

// split-convert a float4 (k-consecutive) and store hi/lo bf16 quads
__device__ __forceinline__ void sts_split4(uint8_t* hi, uint8_t* lo,
                                           int row, int f4, float4 v)
{
    int off = swoff(row, f4 >> 1) + (f4 & 1) * 8;
    __nv_bfloat16 h0 = __float2bfloat16(v.x), h1 = __float2bfloat16(v.y);
    __nv_bfloat16 h2 = __float2bfloat16(v.z), h3 = __float2bfloat16(v.w);
    uint2 hw = { pack_bf16(h0, h1), pack_bf16(h2, h3) };
    uint2 lw = { pack_bf16(__float2bfloat16(v.x - __bfloat162float(h0)),
                           __float2bfloat16(v.y - __bfloat162float(h1))),
                 pack_bf16(__float2bfloat16(v.z - __bfloat162float(h2)),
                           __float2bfloat16(v.w - __bfloat162float(h3))) };
    *(uint2*)(hi + off) = hw;
    *(uint2*)(lo + off) = lw;
}

// ------------------------- split-bf16 tensor-core GEMM (NT) ----------------
// C[M,N] = A[M,K] * B[N,K]^T (+bias)(+relu), fp32 in/out, 3-MMA bf16 split.
// BM=128, BN=64, BK=32, 256 threads, warp tile 64x16 (2x4 warp grid).
// smem per buffer: Ahi 8K | Alo 8K | Bhi 4K | Blo 4K = 24K; double = 48K.
#define GEMM_SMEM 49152

template<bool RELU, bool HASBIAS>
__global__ __launch_bounds__(256, 2)
void mma_gemm_nt(const float* __restrict__ A, const float* __restrict__ B,
                 float* __restrict__ C, const float* __restrict__ bias,
                 int M, int N, int K, long strideB, long strideC)
{
    extern __shared__ uint8_t sm[];
    B += (long)blockIdx.z * strideB;
    C += (long)blockIdx.z * strideC;
    const int bm = blockIdx.y * 128, bn = blockIdx.x * 64;
    const int tid = threadIdx.x, lane = tid & 31, warp = tid >> 5;
    const int wm = (warp & 1) * 64, wn = (warp >> 1) * 16;

    // global prefetch mappings
    const float* apt[4]; int asr[4], asf[4];
    #pragma unroll
    for (int p = 0; p < 4; ++p) {
        int idx = tid + 256 * p;
        asr[p] = idx >> 3; asf[p] = idx & 7;
        apt[p] = A + (long)(bm + asr[p]) * K + asf[p] * 4;
    }
    const float* bpt[2]; int bsr[2], bsf[2];
    #pragma unroll
    for (int p = 0; p < 2; ++p) {
        int idx = tid + 256 * p;
        bsr[p] = idx >> 3; bsf[p] = idx & 7;
        bpt[p] = B + (long)(bn + bsr[p]) * K + bsf[p] * 4;
    }

    const uint32_t sbase = (uint32_t)__cvta_generic_to_shared(sm);

    float acc[4][2][4];
    #pragma unroll
    for (int mt = 0; mt < 4; ++mt)
        #pragma unroll
        for (int n2 = 0; n2 < 2; ++n2)
            #pragma unroll
            for (int j = 0; j < 4; ++j) acc[mt][n2][j] = 0.f;

    // prologue: tile 0
    float4 pa[4], pb[2];
    #pragma unroll
    for (int p = 0; p < 4; ++p) pa[p] = *(const float4*)apt[p];
    #pragma unroll
    for (int p = 0; p < 2; ++p) pb[p] = *(const float4*)bpt[p];
    {
        uint8_t* ah = sm;          uint8_t* al = sm + 8192;
        uint8_t* bh = sm + 16384;  uint8_t* bl = sm + 20480;
        #pragma unroll
        for (int p = 0; p < 4; ++p) sts_split4(ah, al, asr[p], asf[p], pa[p]);
        #pragma unroll
        for (int p = 0; p < 2; ++p) sts_split4(bh, bl, bsr[p], bsf[p], pb[p]);
    }
    __syncthreads();

    const int nt = K / 32;
    int buf = 0;
    for (int t = 0; t < nt; ++t) {
        if (t + 1 < nt) {
            const int ko = (t + 1) * 32;
            #pragma unroll
            for (int p = 0; p < 4; ++p) pa[p] = *(const float4*)(apt[p] + ko);
            #pragma unroll
            for (int p = 0; p < 2; ++p) pb[p] = *(const float4*)(bpt[p] + ko);
        }
        const uint32_t aH = sbase + buf * 24576;
        const uint32_t aL = aH + 8192;
        const uint32_t bH = aH + 16384;
        const uint32_t bL = aH + 20480;
        #pragma unroll
        for (int kk = 0; kk < 2; ++kk) {
            const int kc = kk * 2 + (lane >> 4);
            const int brow = wn + (lane & 15);
            uint32_t bhf[4], blf[4];
            ldsm4(bhf, bH + swoff(brow, kc));
            ldsm4(blf, bL + swoff(brow, kc));
            #pragma unroll
            for (int mt = 0; mt < 4; ++mt) {
                const int arow = wm + mt * 16 + (lane & 15);
                uint32_t ahf[4], alf[4];
                ldsm4(ahf, aH + swoff(arow, kc));
                ldsm4(alf, aL + swoff(arow, kc));
                #pragma unroll
                for (int n2 = 0; n2 < 2; ++n2) {
                    mma_bf16(acc[mt][n2], ahf, bhf[n2], bhf[n2 + 2]);  // hi*hi
                    mma_bf16(acc[mt][n2], ahf, blf[n2], blf[n2 + 2]);  // hi*lo
                    mma_bf16(acc[mt][n2], alf, bhf[n2], bhf[n2 + 2]);  // lo*hi
                }
            }
        }
        if (t + 1 < nt) {
            const int nb = buf ^ 1;
            uint8_t* ah = sm + nb * 24576;  uint8_t* al = ah + 8192;
            uint8_t* bh = ah + 16384;       uint8_t* bl = ah + 20480;
            #pragma unroll
            for (int p = 0; p < 4; ++p) sts_split4(ah, al, asr[p], asf[p], pa[p]);
            #pragma unroll
            for (int p = 0; p < 2; ++p) sts_split4(bh, bl, bsr[p], bsf[p], pb[p]);
            __syncthreads();
            buf = nb;
        }
    }

    // epilogue
    #pragma unroll
    for (int mt = 0; mt < 4; ++mt) {
        const int r0 = bm + wm + mt * 16 + (lane >> 2);
        #pragma unroll
        for (int n2 = 0; n2 < 2; ++n2) {
            const int col = bn + wn + n2 * 8 + (lane & 3) * 2;
            float2 v0 = { acc[mt][n2][0], acc[mt][n2][1] };
            float2 v1 = { acc[mt][n2][2], acc[mt][n2][3] };
            if (HASBIAS) {
                float b0 = bias[col], b1 = bias[col + 1];
                v0.x += b0; v0.y += b1; v1.x += b0; v1.y += b1;
            }
            if (RELU) {
                v0.x = fmaxf(v0.x, 0.f); v0.y = fmaxf(v0.y, 0.f);
                v1.x = fmaxf(v1.x, 0.f); v1.y = fmaxf(v1.y, 0.f);
            }
            *(float2*)(C + (long)r0 * N + col) = v0;
            *(float2*)(C + (long)(r0 + 8) * N + col) = v1;
        }
    }
}

// ------------------------- fused attention (R4, FFMA) ---------------------
#define TQ 16
#define SCP 1028
#define ATT_SMEM ((TQ*SCP + TQ*64 + 4*TQ*64 + 16) * 4)

__global__ __launch_bounds__(256, 2)
void attn_kernel(const float* __restrict__ Q, const float* __restrict__ K,
                 const float* __restrict__ V, float* __restrict__ O)
{
    extern __shared__ float smf[];
    float* sc   = smf;
    float* sq   = smf + TQ*SCP;
    float* pacc = sq + TQ*64;
    float* sinv = pacc + 4*TQ*64;

    const int h = blockIdx.z, b = blockIdx.y;
    const int q0 = blockIdx.x * TQ;
    const int tid = threadIdx.x;
    const long base = ((long)h * NTOK + (long)b * SEQ) * DHEAD;

    ((float4*)sq)[tid] = *(const float4*)(Q + base + (long)q0*64 + tid*4);
    __syncthreads();

    #pragma unroll 1
    for (int mi = 0; mi < 4; ++mi) {
        const int m = tid + mi*256;
        float4 kreg[16];
        const float4* kr = (const float4*)(K + base + (long)m * 64);
        #pragma unroll
        for (int t = 0; t < 16; ++t) kreg[t] = kr[t];
        #pragma unroll
        for (int q = 0; q < TQ; ++q) {
            const float4* q4 = (const float4*)(sq + q*64);
            float4 d = {0.f,0.f,0.f,0.f};
            #pragma unroll
            for (int t = 0; t < 16; ++t) {
                float4 a = q4[t];
                d.x += a.x*kreg[t].x; d.y += a.y*kreg[t].y;
                d.z += a.z*kreg[t].z; d.w += a.w*kreg[t].w;
            }
            sc[q*SCP + m] = (d.x + d.y + d.z + d.w) * INV_TEMPER;
        }
    }
    __syncthreads();

    {
        const int warp = tid >> 5, lane = tid & 31;
        #pragma unroll
        for (int qi = 0; qi < 2; ++qi) {
            const int q = warp*2 + qi;
            float* row = sc + q*SCP;
            float mx = -INFINITY;
            #pragma unroll
            for (int j = 0; j < 32; ++j) mx = fmaxf(mx, row[lane + 32*j]);
            #pragma unroll
            for (int s = 16; s; s >>= 1) mx = fmaxf(mx, __shfl_xor_sync(0xffffffffu, mx, s));
            float sum = 0.f;
            #pragma unroll
            for (int j = 0; j < 32; ++j) {
                float e = __expf(row[lane + 32*j] - mx);
                row[lane + 32*j] = e;
                sum += e;
            }
            #pragma unroll
            for (int s = 16; s; s >>= 1) sum += __shfl_xor_sync(0xffffffffu, sum, s);
            if (lane == 0) sinv[q] = 1.f / sum;
        }
    }
    __syncthreads();

    {
        const int g  = tid >> 6;
        const int q4 = (tid >> 4) & 3;
        const int vq = tid & 15;
        const float* r0 = sc + (q4*4+0)*SCP;
        const float* r1 = sc + (q4*4+1)*SCP;
        const float* r2 = sc + (q4*4+2)*SCP;
        const float* r3 = sc + (q4*4+3)*SCP;
        float4 acc0 = {0,0,0,0}, acc1 = {0,0,0,0}, acc2 = {0,0,0,0}, acc3 = {0,0,0,0};
        const int m0 = g * 256;
        #pragma unroll 4
        for (int m = m0; m < m0 + 256; ++m) {
            float4 vv = *(const float4*)(V + base + (long)m*64 + vq*4);
            float p0 = r0[m], p1 = r1[m], p2 = r2[m], p3 = r3[m];
            acc0.x += p0*vv.x; acc0.y += p0*vv.y; acc0.z += p0*vv.z; acc0.w += p0*vv.w;
            acc1.x += p1*vv.x; acc1.y += p1*vv.y; acc1.z += p1*vv.z; acc1.w += p1*vv.w;
            acc2.x += p2*vv.x; acc2.y += p2*vv.y; acc2.z += p2*vv.z; acc2.w += p2*vv.w;
            acc3.x += p3*vv.x; acc3.y += p3*vv.y; acc3.z += p3*vv.z; acc3.w += p3*vv.w;
        }
        *(float4*)&pacc[(g*TQ + q4*4+0)*64 + vq*4] = acc0;
        *(float4*)&pacc[(g*TQ + q4*4+1)*64 + vq*4] = acc1;
        *(float4*)&pacc[(g*TQ + q4*4+2)*64 + vq*4] = acc2;
        *(float4*)&pacc[(g*TQ + q4*4+3)*64 + vq*4] = acc3;
    }
    __syncthreads();

    #pragma unroll
    for (int s = tid; s < TQ*64; s += 256) {
        const int q = s >> 6;
        float r = (pacc[s] + pacc[TQ*64 + s] + pacc[2*TQ*64 + s] + pacc[3*TQ*64 + s])
                  * sinv[q];
        O[(long)(b*SEQ + q0 + q) * DMODEL + h*64 + (s & 63)] = r;
    }
}

// ------------------------- residual + LayerNorm ---------------------------
__global__ void ln_kernel(const float* __restrict__ X, const float* __restrict__ R,
                          const float* __restrict__ gamma, const float* __restrict__ beta,
                          float* __restrict__ Y)
{
    const long row = blockIdx.x;
    const int tid = threadIdx.x;
    __shared__ float red[128];
    const int i = tid * 4;
    float4 a = *(const float4*)(X + row*DMODEL + i);
    float4 b = *(const float4*)(R + row*DMODEL + i);
    float z0 = a.x + b.x, z1 = a.y + b.y, z2 = a.z + b.z, z3 = a.w + b.w;

    red[tid] = z0 + z1 + z2 + z3; __syncthreads();
    for (int s = 64; s > 0; s >>= 1) {
        if (tid < s) red[tid] += red[tid+s];
        __syncthreads();
    }
    float mu = red[0] * (1.f / DMODEL); __syncthreads();

    float d0 = z0-mu, d1 = z1-mu, d2 = z2-mu, d3 = z3-mu;
    red[tid] = d0*d0 + d1*d1 + d2*d2 + d3*d3; __syncthreads();
    for (int s = 64; s > 0; s >>= 1) {
        if (tid < s) red[tid] += red[tid+s];
        __syncthreads();
    }
    float sigma = sqrtf(red[0] * (1.f / (DMODEL - 1)));   // unbiased (ddof=1)
    float sc = 1.f / (sigma + EPS);

    float4 g4 = *(const float4*)(gamma + i);
    float4 be = *(const float4*)(beta + i);
    float4 y;
    y.x = d0 * sc * g4.x + be.x;
    y.y = d1 * sc * g4.y + be.y;
    y.z = d2 * sc * g4.z + be.z;
    y.w = d3 * sc * g4.w + be.w;
    *(float4*)(Y + row*DMODEL + i) = y;
}

// ------------------------- launch ------------------------------------------
extern "C" void kernel_launch(void* const* d_in, const int* in_sizes, int n_in,
                              void* d_out, int out_size)
{
    (void)in_sizes; (void)n_in; (void)out_size;
    const float* x    = (const float*)d_in[0];
    const float* pos  = (const float*)d_in[1];
    const float* wq   = (const float*)d_in[2];
    const float* wk   = (const float*)d_in[3];
    const float* wv   = (const float*)d_in[4];
    const float* ln1a = (const float*)d_in[5];
    const float* ln1b = (const float*)d_in[6];
    const float* w1   = (const float*)d_in[7];
    const float* b1   = (const float*)d_in[8];
    const float* w2   = (const float*)d_in[9];
    const float* b2   = (const float*)d_in[10];
    const float* ln2a = (const float*)d_in[11];
    const float* ln2b = (const float*)d_in[12];
    float* out = (float*)d_out;

    float *gx, *gq, *gk, *gv, *ga, *gh, *go, *wqt, *wkt, *wvt;
    cudaGetSymbolAddress((void**)&gx, g_x);
    cudaGetSymbolAddress((void**)&gq, g_q);
    cudaGetSymbolAddress((void**)&gk, g_k);
    cudaGetSymbolAddress((void**)&gv, g_v);
    cudaGetSymbolAddress((void**)&ga, g_att);
    cudaGetSymbolAddress((void**)&gh, g_h);
    cudaGetSymbolAddress((void**)&go, g_o);
    cudaGetSymbolAddress((void**)&wqt, g_wqt);
    cudaGetSymbolAddress((void**)&wkt, g_wkt);
    cudaGetSymbolAddress((void**)&wvt, g_wvt);

    static bool attr_set = false;
    if (!attr_set) {
        cudaFuncSetAttribute(attn_kernel,
                             cudaFuncAttributeMaxDynamicSharedMemorySize, ATT_SMEM);
        cudaFuncSetAttribute(mma_gemm_nt<false,false>,
                             cudaFuncAttributeMaxDynamicSharedMemorySize, GEMM_SMEM);
        cudaFuncSetAttribute(mma_gemm_nt<true,true>,
                             cudaFuncAttributeMaxDynamicSharedMemorySize, GEMM_SMEM);
        cudaFuncSetAttribute(mma_gemm_nt<false,true>,
                             cudaFuncAttributeMaxDynamicSharedMemorySize, GEMM_SMEM);
        attr_set = true;
    }

    add_pos_kernel<<<NTOK*DMODEL/512, 512>>>(x, pos, gx);

    // transpose qkv weights [L*H][512][64] -> [L*H][64][512]
    {
        dim3 tg(DHEAD/32, DMODEL/32, NLAYERS*NHEAD);
        transpose_kernel<<<tg, dim3(32,8)>>>(wq, wqt, DMODEL, DHEAD);
        transpose_kernel<<<tg, dim3(32,8)>>>(wk, wkt, DMODEL, DHEAD);
        transpose_kernel<<<tg, dim3(32,8)>>>(wv, wvt, DMODEL, DHEAD);
    }

    const long wqkv_head  = (long)DMODEL * DHEAD;
    const long wqkv_layer = (long)NHEAD * wqkv_head;
    const long qkv_head   = (long)NTOK * DHEAD;

    for (int i = 0; i < NLAYERS; ++i) {
        // QKV projections: per-head NT GEMM [4096,512] x [64,512]^T
        dim3 gqkv(1, NTOK/128, NHEAD);
        mma_gemm_nt<false,false><<<gqkv, 256, GEMM_SMEM>>>(
            gx, wqt + i*wqkv_layer, gq, nullptr,
            NTOK, DHEAD, DMODEL, wqkv_head, qkv_head);
        mma_gemm_nt<false,false><<<gqkv, 256, GEMM_SMEM>>>(
            gx, wkt + i*wqkv_layer, gk, nullptr,
            NTOK, DHEAD, DMODEL, wqkv_head, qkv_head);
        mma_gemm_nt<false,false><<<gqkv, 256, GEMM_SMEM>>>(
            gx, wvt + i*wqkv_layer, gv, nullptr,
            NTOK, DHEAD, DMODEL, wqkv_head, qkv_head);

        attn_kernel<<<dim3(SEQ/TQ, BATCH, NHEAD), 256, ATT_SMEM>>>(gq, gk, gv, ga);

        ln_kernel<<<NTOK, 128>>>(ga, gx, ln1a + i*DMODEL, ln1b + i*DMODEL, gx);

        // FFN1: h = relu(x @ w1^T + b1), w1 is [1024,512] NT-native
        mma_gemm_nt<true,true><<<dim3(DINNER/64, NTOK/128, 1), 256, GEMM_SMEM>>>(
            gx, w1 + (long)i*DINNER*DMODEL, gh, b1 + i*DINNER,
            NTOK, DINNER, DMODEL, 0, 0);
        // FFN2: o = h @ w2^T + b2, w2 is [512,1024] NT-native
        mma_gemm_nt<false,true><<<dim3(DMODEL/64, NTOK/128, 1), 256, GEMM_SMEM>>>(
            gh, w2 + (long)i*DMODEL*DINNER, go, b2 + i*DMODEL,
            NTOK, DMODEL, DINNER, 0, 0);

        ln_kernel<<<NTOK, 128>>>(go, gx, ln2a + i*DMODEL, ln2b + i*DMODEL, gx);
    }

    cudaMemcpyAsync(out, gx, (size_t)NTOK*DMODEL*sizeof(float),
                    cudaMemcpyDeviceToDevice);
}

// round 7
// speedup vs baseline: 6.4460x; 2.0930x over previous
#include <cuda_runtime.h>
#include <cuda_bf16.h>
#include <math.h>
#include <stdint.h>

#define BATCH 4
#define SEQ 1024
#define DMODEL 512
#define NHEAD 8
#define DHEAD 64
#define DINNER 1024
#define NLAYERS 2
#define NTOK (BATCH*SEQ)          // 4096
#define EPS 1e-3f
#define INV_TEMPER 0.044194173824159216f   // 1/sqrt(512)

// ------------------------- scratch (device globals; no runtime alloc) -----
__device__ float g_x  [NTOK*DMODEL];
__device__ float g_att[NTOK*DMODEL];
__device__ float g_h  [NTOK*DINNER];
__device__ float g_o  [NTOK*DMODEL];
// transposed qkv weights: [L][3][H][DHEAD][DMODEL]
__device__ float g_wqkvt[NLAYERS*3*NHEAD*DHEAD*DMODEL];
// split-bf16 QKV activations: [3][H][NTOK][DHEAD]
__device__ __nv_bfloat16 g_qkv_h[3*NHEAD*NTOK*DHEAD];
__device__ __nv_bfloat16 g_qkv_l[3*NHEAD*NTOK*DHEAD];

// ------------------------- x + pos_enc ------------------------------------
__global__ void add_pos_kernel(const float* __restrict__ x,
                               const float* __restrict__ pos,
                               float* __restrict__ y)
{
    int idx = blockIdx.x * 512 + threadIdx.x;
    y[idx] = x[idx] + pos[idx & (SEQ*DMODEL - 1)];
}

// ------------------------- transpose [512,64] -> [64,512] into qkv slot ---
__global__ void transpose_kernel(const float* __restrict__ in, float* __restrict__ out,
                                 int w)
{
    __shared__ float tile[32][33];
    const int l = blockIdx.z / NHEAD, h = blockIdx.z % NHEAD;
    const float* ip = in  + (long)blockIdx.z * DMODEL * DHEAD;
    float*       op = out + (long)((l*3 + w)*NHEAD + h) * DHEAD * DMODEL;
    int c0 = blockIdx.x * 32, r0 = blockIdx.y * 32;
    for (int i = threadIdx.y; i < 32; i += 8)
        tile[i][threadIdx.x] = ip[(long)(r0 + i) * DHEAD + c0 + threadIdx.x];
    __syncthreads();
    for (int i = threadIdx.y; i < 32; i += 8)
        op[(long)(c0 + i) * DMODEL + r0 + threadIdx.x] = tile[threadIdx.x][i];
}

// ------------------------- mma / ldsm helpers -----------------------------
__device__ __forceinline__ void ldsm4(uint32_t* r, uint32_t addr)
{
    asm volatile("ldmatrix.sync.aligned.m8n8.x4.shared.b16 {%0,%1,%2,%3}, [%4];"
        : "=r"(r[0]), "=r"(r[1]), "=r"(r[2]), "=r"(r[3]) : "r"(addr));
}
__device__ __forceinline__ void ldsm4t(uint32_t* r, uint32_t addr)
{
    asm volatile("ldmatrix.sync.aligned.m8n8.x4.trans.shared.b16 {%0,%1,%2,%3}, [%4];"
        : "=r"(r[0]), "=r"(r[1]), "=r"(r[2]), "=r"(r[3]) : "r"(addr));
}
__device__ __forceinline__ void mma_bf16(float* c, const uint32_t* a,
                                         uint32_t b0, uint32_t b1)
{
    asm volatile(
        "mma.sync.aligned.m16n8k16.row.col.f32.bf16.bf16.f32 "
        "{%0,%1,%2,%3}, {%4,%5,%6,%7}, {%8,%9}, {%0,%1,%2,%3};\n"
        : "+f"(c[0]), "+f"(c[1]), "+f"(c[2]), "+f"(c[3])
        : "r"(a[0]), "r"(a[1]), "r"(a[2]), "r"(a[3]), "r"(b0), "r"(b1));
}
__device__ __forceinline__ uint32_t pack_bf16(__nv_bfloat16 a, __nv_bfloat16 b)
{
    __nv_bfloat162 t = __halves2bfloat162(a, b);
    return *(uint32_t*)&t;
}
__device__ __forceinline__ void packsplit(float x, float y, uint32_t& hi, uint32_t& lo)
{
    __nv_bfloat16 hx = __float2bfloat16(x), hy = __float2bfloat16(y);
    hi = pack_bf16(hx, hy);
    lo = pack_bf16(__float2bfloat16(x - __bfloat162float(hx)),
                   __float2bfloat16(y - __bfloat162float(hy)));
}
__device__ __forceinline__ void cpa16(uint32_t dst, const void* src)
{
    asm volatile("cp.async.cg.shared.global [%0], [%1], 16;\n" :: "r"(dst), "l"(src));
}
__device__ __forceinline__ void cpa_commit()
{
    asm volatile("cp.async.commit_group;\n");
}
template<int N> __device__ __forceinline__ void cpa_wait()
{
    asm volatile("cp.async.wait_group %0;\n" :: "n"(N));
}

// GEMM smem swizzle: 64B rows (32 bf16), 4x16B chunks
__device__ __forceinline__ int swoff(int row, int chunk)
{
    return row * 64 + ((chunk ^ ((row >> 1) & 3)) * 16);
}
// attention plane swizzle: 128B rows (64 bf16), 8x16B chunks
__device__ __forceinline__ uint32_t swz128(int row, int c16)
{
    return (uint32_t)(row * 128 + ((c16 ^ (row & 7)) * 16));
}

// split-convert a float4 (k-consecutive) and store hi/lo bf16 quads
__device__ __forceinline__ void sts_split4(uint8_t* hi, uint8_t* lo,
                                           int row, int f4, float4 v)
{
    int off = swoff(row, f4 >> 1) + (f4 & 1) * 8;
    __nv_bfloat16 h0 = __float2bfloat16(v.x), h1 = __float2bfloat16(v.y);
    __nv_bfloat16 h2 = __float2bfloat16(v.z), h3 = __float2bfloat16(v.w);
    uint2 hw = { pack_bf16(h0, h1), pack_bf16(h2, h3) };
    uint2 lw = { pack_bf16(__float2bfloat16(v.x - __bfloat162float(h0)),
                           __float2bfloat16(v.y - __bfloat162float(h1))),
                 pack_bf16(__float2bfloat16(v.z - __bfloat162float(h2)),
                           __float2bfloat16(v.w - __bfloat162float(h3))) };
    *(uint2*)(hi + off) = hw;
    *(uint2*)(lo + off) = lw;
}

// ------------------------- split-bf16 tensor-core GEMM (NT) ----------------
// C[M,N] = A[M,K] * B[N,K]^T, fp32 in, fp32 out or split-bf16 planes out.
#define GEMM_SMEM 49152

template<bool RELU, bool HASBIAS, bool SPLIT>
__global__ __launch_bounds__(256, 2)
void mma_gemm_nt(const float* __restrict__ A, const float* __restrict__ B,
                 float* __restrict__ C, const float* __restrict__ bias,
                 __nv_bfloat16* __restrict__ Chi, __nv_bfloat16* __restrict__ Clo,
                 int M, int N, int K, long strideB, long strideC)
{
    extern __shared__ uint8_t sm[];
    B += (long)blockIdx.z * strideB;
    if (SPLIT) { Chi += (long)blockIdx.z * strideC; Clo += (long)blockIdx.z * strideC; }
    else       { C   += (long)blockIdx.z * strideC; }
    const int bm = blockIdx.y * 128, bn = blockIdx.x * 64;
    const int tid = threadIdx.x, lane = tid & 31, warp = tid >> 5;
    const int wm = (warp & 1) * 64, wn = (warp >> 1) * 16;

    const float* apt[4]; int asr[4], asf[4];
    #pragma unroll
    for (int p = 0; p < 4; ++p) {
        int idx = tid + 256 * p;
        asr[p] = idx >> 3; asf[p] = idx & 7;
        apt[p] = A + (long)(bm + asr[p]) * K + asf[p] * 4;
    }
    const float* bpt[2]; int bsr[2], bsf[2];
    #pragma unroll
    for (int p = 0; p < 2; ++p) {
        int idx = tid + 256 * p;
        bsr[p] = idx >> 3; bsf[p] = idx & 7;
        bpt[p] = B + (long)(bn + bsr[p]) * K + bsf[p] * 4;
    }

    const uint32_t sbase = (uint32_t)__cvta_generic_to_shared(sm);

    float acc[4][2][4];
    #pragma unroll
    for (int mt = 0; mt < 4; ++mt)
        #pragma unroll
        for (int n2 = 0; n2 < 2; ++n2)
            #pragma unroll
            for (int j = 0; j < 4; ++j) acc[mt][n2][j] = 0.f;

    float4 pa[4], pb[2];
    #pragma unroll
    for (int p = 0; p < 4; ++p) pa[p] = *(const float4*)apt[p];
    #pragma unroll
    for (int p = 0; p < 2; ++p) pb[p] = *(const float4*)bpt[p];
    {
        uint8_t* ah = sm;          uint8_t* al = sm + 8192;
        uint8_t* bh = sm + 16384;  uint8_t* bl = sm + 20480;
        #pragma unroll
        for (int p = 0; p < 4; ++p) sts_split4(ah, al, asr[p], asf[p], pa[p]);
        #pragma unroll
        for (int p = 0; p < 2; ++p) sts_split4(bh, bl, bsr[p], bsf[p], pb[p]);
    }
    __syncthreads();

    const int nt = K / 32;
    int buf = 0;
    for (int t = 0; t < nt; ++t) {
        if (t + 1 < nt) {
            const int ko = (t + 1) * 32;
            #pragma unroll
            for (int p = 0; p < 4; ++p) pa[p] = *(const float4*)(apt[p] + ko);
            #pragma unroll
            for (int p = 0; p < 2; ++p) pb[p] = *(const float4*)(bpt[p] + ko);
        }
        const uint32_t aH = sbase + buf * 24576;
        const uint32_t aL = aH + 8192;
        const uint32_t bH = aH + 16384;
        const uint32_t bL = aH + 20480;
        #pragma unroll
        for (int kk = 0; kk < 2; ++kk) {
            const int kc = kk * 2 + (lane >> 4);
            const int brow = wn + (lane & 15);
            uint32_t bhf[4], blf[4];
            ldsm4(bhf, bH + swoff(brow, kc));
            ldsm4(blf, bL + swoff(brow, kc));
            #pragma unroll
            for (int mt = 0; mt < 4; ++mt) {
                const int arow = wm + mt * 16 + (lane & 15);
                uint32_t ahf[4], alf[4];
                ldsm4(ahf, aH + swoff(arow, kc));
                ldsm4(alf, aL + swoff(arow, kc));
                #pragma unroll
                for (int n2 = 0; n2 < 2; ++n2) {
                    mma_bf16(acc[mt][n2], ahf, bhf[n2], bhf[n2 + 2]);
                    mma_bf16(acc[mt][n2], ahf, blf[n2], blf[n2 + 2]);
                    mma_bf16(acc[mt][n2], alf, bhf[n2], bhf[n2 + 2]);
                }
            }
        }
        if (t + 1 < nt) {
            const int nb = buf ^ 1;
            uint8_t* ah = sm + nb * 24576;  uint8_t* al = ah + 8192;
            uint8_t* bh = ah + 16384;       uint8_t* bl = ah + 20480;
            #pragma unroll
            for (int p = 0; p < 4; ++p) sts_split4(ah, al, asr[p], asf[p], pa[p]);
            #pragma unroll
            for (int p = 0; p < 2; ++p) sts_split4(bh, bl, bsr[p], bsf[p], pb[p]);
            __syncthreads();
            buf = nb;
        }
    }

    #pragma unroll
    for (int mt = 0; mt < 4; ++mt) {
        const int r0 = bm + wm + mt * 16 + (lane >> 2);
        #pragma unroll
        for (int n2 = 0; n2 < 2; ++n2) {
            const int col = bn + wn + n2 * 8 + (lane & 3) * 2;
            float2 v0 = { acc[mt][n2][0], acc[mt][n2][1] };
            float2 v1 = { acc[mt][n2][2], acc[mt][n2][3] };
            if (HASBIAS) {
                float b0 = bias[col], b1 = bias[col + 1];
                v0.x += b0; v0.y += b1; v1.x += b0; v1.y += b1;
            }
            if (RELU) {
                v0.x = fmaxf(v0.x, 0.f); v0.y = fmaxf(v0.y, 0.f);
                v1.x = fmaxf(v1.x, 0.f); v1.y = fmaxf(v1.y, 0.f);
            }
            if (SPLIT) {
                __nv_bfloat16 h0 = __float2bfloat16(v0.x), h1 = __float2bfloat16(v0.y);
                __nv_bfloat16 h2 = __float2bfloat16(v1.x), h3 = __float2bfloat16(v1.y);
                *(__nv_bfloat162*)(Chi + (long)r0 * N + col) = __halves2bfloat162(h0, h1);
                *(__nv_bfloat162*)(Chi + (long)(r0+8) * N + col) = __halves2bfloat162(h2, h3);
                *(__nv_bfloat162*)(Clo + (long)r0 * N + col) =
                    __halves2bfloat162(__float2bfloat16(v0.x - __bfloat162float(h0)),
                                       __float2bfloat16(v0.y - __bfloat162float(h1)));
                *(__nv_bfloat162*)(Clo + (long)(r0+8) * N + col) =
                    __halves2bfloat162(__float2bfloat16(v1.x - __bfloat162float(h2)),
                                       __float2bfloat16(v1.y - __bfloat162float(h3)));
            } else {
                *(float2*)(C + (long)r0 * N + col) = v0;
                *(float2*)(C + (long)(r0 + 8) * N + col) = v1;
            }
        }
    }
}

// ------------------------- FA2 tensor-core attention ----------------------
// block = 128 q rows x (b,h). 8 warps, warp owns 16 q rows. K/V chunks of 128.
// smem: stage0 64KB | stage1 64KB | Qhi 16KB | Qlo 16KB = 160KB
#define FA_SMEM 163840
#define ST_KH 0
#define ST_KL 16384
#define ST_VH 32768
#define ST_VL 49152

__global__ __launch_bounds__(256, 1)
void fa2_kernel(const __nv_bfloat16* __restrict__ QKVh,
                const __nv_bfloat16* __restrict__ QKVl,
                float* __restrict__ O)
{
    extern __shared__ uint8_t sm[];
    const uint32_t sbase = (uint32_t)__cvta_generic_to_shared(sm);
    const uint32_t qoffH = 131072, qoffL = 147456;

    const int h = blockIdx.z, b = blockIdx.y;
    const int q0 = blockIdx.x * 128;
    const int tid = threadIdx.x, lane = tid & 31, warp = tid >> 5;

    const long planeQ = ((long)h * NTOK + (long)b * SEQ) * DHEAD;
    const long planeK = ((long)(NHEAD + h) * NTOK + (long)b * SEQ) * DHEAD;
    const long planeV = ((long)(2*NHEAD + h) * NTOK + (long)b * SEQ) * DHEAD;

    // per-thread copy slots: 4x16B per 16KB plane
    int crow[4], cc16[4];
    #pragma unroll
    for (int p = 0; p < 4; ++p) {
        int ci = tid + p * 256;
        crow[p] = ci >> 3; cc16[p] = ci & 7;
    }

    // prologue group 1: Q planes (rows q0..q0+127)
    #pragma unroll
    for (int p = 0; p < 4; ++p) {
        cpa16(sbase + qoffH + swz128(crow[p], cc16[p]),
              QKVh + planeQ + (long)(q0 + crow[p]) * 64 + cc16[p] * 8);
        cpa16(sbase + qoffL + swz128(crow[p], cc16[p]),
              QKVl + planeQ + (long)(q0 + crow[p]) * 64 + cc16[p] * 8);
    }
    cpa_commit();
    // prologue group 2: chunk 0 K/V into stage 0
    #pragma unroll
    for (int p = 0; p < 4; ++p) {
        long ro = (long)crow[p] * 64 + cc16[p] * 8;
        uint32_t so = swz128(crow[p], cc16[p]);
        cpa16(sbase + ST_KH + so, QKVh + planeK + ro);
        cpa16(sbase + ST_KL + so, QKVl + planeK + ro);
        cpa16(sbase + ST_VH + so, QKVh + planeV + ro);
        cpa16(sbase + ST_VL + so, QKVl + planeV + ro);
    }
    cpa_commit();

    cpa_wait<1>();          // Q ready
    __syncthreads();

    // Q fragments (held in regs for the whole kernel)
    uint32_t qh[4][4], ql[4][4];
    {
        const int qrow = warp * 16 + (lane & 15);
        #pragma unroll
        for (int ks = 0; ks < 4; ++ks) {
            ldsm4(qh[ks], sbase + qoffH + swz128(qrow, 2*ks + (lane >> 4)));
            ldsm4(ql[ks], sbase + qoffL + swz128(qrow, 2*ks + (lane >> 4)));
        }
    }

    float o[8][4];
    #pragma unroll
    for (int vt = 0; vt < 8; ++vt)
        #pragma unroll
        for (int j = 0; j < 4; ++j) o[vt][j] = 0.f;
    float run_m0 = -INFINITY, run_m1 = -INFINITY;
    float run_l0 = 0.f, run_l1 = 0.f;

    #pragma unroll 1
    for (int c = 0; c < 8; ++c) {
        const uint32_t stg = sbase + (c & 1) * 65536;
        if (c < 7) {                       // prefetch chunk c+1
            const uint32_t nst = sbase + ((c + 1) & 1) * 65536;
            const long m0 = (long)(c + 1) * 128;
            #pragma unroll
            for (int p = 0; p < 4; ++p) {
                long ro = (m0 + crow[p]) * 64 + cc16[p] * 8;
                uint32_t so = swz128(crow[p], cc16[p]);
                cpa16(nst + ST_KH + so, QKVh + planeK + ro);
                cpa16(nst + ST_KL + so, QKVl + planeK + ro);
                cpa16(nst + ST_VH + so, QKVh + planeV + ro);
                cpa16(nst + ST_VL + so, QKVl + planeV + ro);
            }
            cpa_commit();
            cpa_wait<1>();
        } else {
            cpa_wait<0>();
        }
        __syncthreads();

        // ---- S = Q K^T (split bf16, 3 terms), 16 n8-tiles
        float s[16][4];
        #pragma unroll
        for (int t = 0; t < 16; ++t)
            #pragma unroll
            for (int j = 0; j < 4; ++j) s[t][j] = 0.f;
        #pragma unroll
        for (int g = 0; g < 8; ++g) {
            const int krow = g * 16 + (lane & 15);
            #pragma unroll
            for (int ks = 0; ks < 4; ++ks) {
                const uint32_t so = swz128(krow, 2*ks + (lane >> 4));
                uint32_t khf[4], klf[4];
                ldsm4(khf, stg + ST_KH + so);
                ldsm4(klf, stg + ST_KL + so);
                #pragma unroll
                for (int n2 = 0; n2 < 2; ++n2) {
                    float* st = s[g*2 + n2];
                    mma_bf16(st, qh[ks], khf[n2], khf[n2 + 2]);
                    mma_bf16(st, qh[ks], klf[n2], klf[n2 + 2]);
                    mma_bf16(st, ql[ks], khf[n2], khf[n2 + 2]);
                }
            }
        }

        // ---- online softmax (rows r = lane>>2, r+8)
        float mx0 = -INFINITY, mx1 = -INFINITY;
        #pragma unroll
        for (int t = 0; t < 16; ++t) {
            s[t][0] *= INV_TEMPER; s[t][1] *= INV_TEMPER;
            s[t][2] *= INV_TEMPER; s[t][3] *= INV_TEMPER;
            mx0 = fmaxf(mx0, fmaxf(s[t][0], s[t][1]));
            mx1 = fmaxf(mx1, fmaxf(s[t][2], s[t][3]));
        }
        mx0 = fmaxf(mx0, __shfl_xor_sync(0xffffffffu, mx0, 1));
        mx0 = fmaxf(mx0, __shfl_xor_sync(0xffffffffu, mx0, 2));
        mx1 = fmaxf(mx1, __shfl_xor_sync(0xffffffffu, mx1, 1));
        mx1 = fmaxf(mx1, __shfl_xor_sync(0xffffffffu, mx1, 2));

        const float nm0 = fmaxf(run_m0, mx0);
        const float nm1 = fmaxf(run_m1, mx1);
        const float sc0 = __expf(run_m0 - nm0);
        const float sc1 = __expf(run_m1 - nm1);
        run_m0 = nm0; run_m1 = nm1;

        float ps0 = 0.f, ps1 = 0.f;
        #pragma unroll
        for (int t = 0; t < 16; ++t) {
            float p0 = __expf(s[t][0] - nm0); s[t][0] = p0;
            float p1 = __expf(s[t][1] - nm0); s[t][1] = p1;
            float p2 = __expf(s[t][2] - nm1); s[t][2] = p2;
            float p3 = __expf(s[t][3] - nm1); s[t][3] = p3;
            ps0 += p0 + p1; ps1 += p2 + p3;
        }
        run_l0 = run_l0 * sc0 + ps0;
        run_l1 = run_l1 * sc1 + ps1;
        #pragma unroll
        for (int vt = 0; vt < 8; ++vt) {
            o[vt][0] *= sc0; o[vt][1] *= sc0;
            o[vt][2] *= sc1; o[vt][3] *= sc1;
        }

        // ---- O += P V (P split from regs, V split via trans ldsm)
        #pragma unroll
        for (int ks = 0; ks < 8; ++ks) {
            uint32_t ah[4], al[4];
            packsplit(s[2*ks][0],   s[2*ks][1],   ah[0], al[0]);
            packsplit(s[2*ks][2],   s[2*ks][3],   ah[1], al[1]);
            packsplit(s[2*ks+1][0], s[2*ks+1][1], ah[2], al[2]);
            packsplit(s[2*ks+1][2], s[2*ks+1][3], ah[3], al[3]);
            const int vrow = ks * 16 + (lane & 15);
            #pragma unroll
            for (int vg = 0; vg < 4; ++vg) {
                const uint32_t so = swz128(vrow, vg*2 + (lane >> 4));
                uint32_t vhf[4], vlf[4];
                ldsm4t(vhf, stg + ST_VH + so);
                ldsm4t(vlf, stg + ST_VL + so);
                #pragma unroll
                for (int n2 = 0; n2 < 2; ++n2) {
                    float* ot = o[vg*2 + n2];
                    mma_bf16(ot, ah, vhf[2*n2], vhf[2*n2 + 1]);
                    mma_bf16(ot, ah, vlf[2*n2], vlf[2*n2 + 1]);
                    mma_bf16(ot, al, vhf[2*n2], vhf[2*n2 + 1]);
                }
            }
        }
        __syncthreads();   // stage consumed; safe to overwrite next iter
    }

    // ---- finalize: reduce l across quad, normalize, write concat output
    run_l0 += __shfl_xor_sync(0xffffffffu, run_l0, 1);
    run_l0 += __shfl_xor_sync(0xffffffffu, run_l0, 2);
    run_l1 += __shfl_xor_sync(0xffffffffu, run_l1, 1);
    run_l1 += __shfl_xor_sync(0xffffffffu, run_l1, 2);
    const float inv0 = 1.f / run_l0, inv1 = 1.f / run_l1;

    const int r  = q0 + warp * 16 + (lane >> 2);
    const int cb = h * 64 + (lane & 3) * 2;
    #pragma unroll
    for (int vt = 0; vt < 8; ++vt) {
        float2 v0 = { o[vt][0] * inv0, o[vt][1] * inv0 };
        float2 v1 = { o[vt][2] * inv1, o[vt][3] * inv1 };
        *(float2*)(O + ((long)b*SEQ + r)     * DMODEL + cb + vt*8) = v0;
        *(float2*)(O + ((long)b*SEQ + r + 8) * DMODEL + cb + vt*8) = v1;
    }
}

// ------------------------- residual + LayerNorm ---------------------------
__global__ void ln_kernel(const float* __restrict__ X, const float* __restrict__ R,
                          const float* __restrict__ gamma, const float* __restrict__ beta,
                          float* __restrict__ Y)
{
    const long row = blockIdx.x;
    const int tid = threadIdx.x;
    __shared__ float red[128];
    const int i = tid * 4;
    float4 a = *(const float4*)(X + row*DMODEL + i);
    float4 b = *(const float4*)(R + row*DMODEL + i);
    float z0 = a.x + b.x, z1 = a.y + b.y, z2 = a.z + b.z, z3 = a.w + b.w;

    red[tid] = z0 + z1 + z2 + z3; __syncthreads();
    for (int s = 64; s > 0; s >>= 1) {
        if (tid < s) red[tid] += red[tid+s];
        __syncthreads();
    }
    float mu = red[0] * (1.f / DMODEL); __syncthreads();

    float d0 = z0-mu, d1 = z1-mu, d2 = z2-mu, d3 = z3-mu;
    red[tid] = d0*d0 + d1*d1 + d2*d2 + d3*d3; __syncthreads();
    for (int s = 64; s > 0; s >>= 1) {
        if (tid < s) red[tid] += red[tid+s];
        __syncthreads();
    }
    float sigma = sqrtf(red[0] * (1.f / (DMODEL - 1)));   // unbiased (ddof=1)
    float sc = 1.f / (sigma + EPS);

    float4 g4 = *(const float4*)(gamma + i);
    float4 be = *(const float4*)(beta + i);
    float4 y;
    y.x = d0 * sc * g4.x + be.x;
    y.y = d1 * sc * g4.y + be.y;
    y.z = d2 * sc * g4.z + be.z;
    y.w = d3 * sc * g4.w + be.w;
    *(float4*)(Y + row*DMODEL + i) = y;
}

// ------------------------- launch ------------------------------------------
extern "C" void kernel_launch(void* const* d_in, const int* in_sizes, int n_in,
                              void* d_out, int out_size)
{
    (void)in_sizes; (void)n_in; (void)out_size;
    const float* x    = (const float*)d_in[0];
    const float* pos  = (const float*)d_in[1];
    const float* wq   = (const float*)d_in[2];
    const float* wk   = (const float*)d_in[3];
    const float* wv   = (const float*)d_in[4];
    const float* ln1a = (const float*)d_in[5];
    const float* ln1b = (const float*)d_in[6];
    const float* w1   = (const float*)d_in[7];
    const float* b1   = (const float*)d_in[8];
    const float* w2   = (const float*)d_in[9];
    const float* b2   = (const float*)d_in[10];
    const float* ln2a = (const float*)d_in[11];
    const float* ln2b = (const float*)d_in[12];
    float* out = (float*)d_out;

    float *gx, *ga, *gh, *go, *wqkvt;
    __nv_bfloat16 *qkvh, *qkvl;
    cudaGetSymbolAddress((void**)&gx, g_x);
    cudaGetSymbolAddress((void**)&ga, g_att);
    cudaGetSymbolAddress((void**)&gh, g_h);
    cudaGetSymbolAddress((void**)&go, g_o);
    cudaGetSymbolAddress((void**)&wqkvt, g_wqkvt);
    cudaGetSymbolAddress((void**)&qkvh, g_qkv_h);
    cudaGetSymbolAddress((void**)&qkvl, g_qkv_l);

    static bool attr_set = false;
    if (!attr_set) {
        cudaFuncSetAttribute(fa2_kernel,
                             cudaFuncAttributeMaxDynamicSharedMemorySize, FA_SMEM);
        cudaFuncSetAttribute(mma_gemm_nt<false,false,true>,
                             cudaFuncAttributeMaxDynamicSharedMemorySize, GEMM_SMEM);
        cudaFuncSetAttribute(mma_gemm_nt<true,true,false>,
                             cudaFuncAttributeMaxDynamicSharedMemorySize, GEMM_SMEM);
        cudaFuncSetAttribute(mma_gemm_nt<false,true,false>,
                             cudaFuncAttributeMaxDynamicSharedMemorySize, GEMM_SMEM);
        attr_set = true;
    }

    add_pos_kernel<<<NTOK*DMODEL/512, 512>>>(x, pos, gx);

    // transpose qkv weights into [L][3][H][64][512]
    {
        dim3 tg(DHEAD/32, DMODEL/32, NLAYERS*NHEAD);
        transpose_kernel<<<tg, dim3(32,8)>>>(wq, wqkvt, 0);
        transpose_kernel<<<tg, dim3(32,8)>>>(wk, wqkvt, 1);
        transpose_kernel<<<tg, dim3(32,8)>>>(wv, wqkvt, 2);
    }

    const long wqkv_mat  = (long)DHEAD * DMODEL;           // per (w,h) slot
    const long wqkv_layer = 3L * NHEAD * wqkv_mat;
    const long qkv_mat   = (long)NTOK * DHEAD;

    for (int i = 0; i < NLAYERS; ++i) {
        // fused QKV: 24 matrices [4096,512]x[64,512]^T -> split bf16 planes
        mma_gemm_nt<false,false,true><<<dim3(1, NTOK/128, 3*NHEAD), 256, GEMM_SMEM>>>(
            gx, wqkvt + i*wqkv_layer, nullptr, nullptr, qkvh, qkvl,
            NTOK, DHEAD, DMODEL, wqkv_mat, qkv_mat);

        // flash attention + concat heads
        fa2_kernel<<<dim3(SEQ/128, BATCH, NHEAD), 256, FA_SMEM>>>(qkvh, qkvl, ga);

        ln_kernel<<<NTOK, 128>>>(ga, gx, ln1a + i*DMODEL, ln1b + i*DMODEL, gx);

        // FFN1: h = relu(x @ w1^T + b1)
        mma_gemm_nt<true,true,false><<<dim3(DINNER/64, NTOK/128, 1), 256, GEMM_SMEM>>>(
            gx, w1 + (long)i*DINNER*DMODEL, gh, b1 + i*DINNER, nullptr, nullptr,
            NTOK, DINNER, DMODEL, 0, 0);
        // FFN2: o = h @ w2^T + b2
        mma_gemm_nt<false,true,false><<<dim3(DMODEL/64, NTOK/128, 1), 256, GEMM_SMEM>>>(
            gh, w2 + (long)i*DMODEL*DINNER, go, b2 + i*DMODEL, nullptr, nullptr,
            NTOK, DMODEL, DINNER, 0, 0);

        ln_kernel<<<NTOK, 128>>>(go, gx, ln2a + i*DMODEL, ln2b + i*DMODEL, gx);
    }

    cudaMemcpyAsync(out, gx, (size_t)NTOK*DMODEL*sizeof(float),
                    cudaMemcpyDeviceToDevice);
}